// round 14
// baseline (speedup 1.0000x reference)
#include <cuda_runtime.h>
#include <cuda_bf16.h>
#include <math.h>
#include <stdint.h>

// ---------------- problem constants ----------------
#define NB        2
#define D_MODEL   512
#define D_STATE   128
#define D_CONV    4
#define HEADDIM   64
#define D_INNER   1024
#define NHEADS    16
#define CONV_DIM  1280
#define D_IN_PROJ 2320
#define NPAD_IN   2432
#define LABELS    1000
#define NPAD_HD   1024
#define BATCH     2
#define SEQ       512
#define MROWS     (BATCH*SEQ)
#define QCH       64
#define NCHUNK    (SEQ/QCH)     // 8
#define BH        (BATCH*NHEADS)// 32
#define BC        (BATCH*NCHUNK)// 16

// ---------------- scratch ----------------
__device__ float g_x  [MROWS * D_MODEL];
__device__ float g_zx [MROWS * D_IN_PROJ];
__device__ float g_xbc[MROWS * CONV_DIM];
__device__ float g_dt [MROWS * NHEADS];
__device__ float g_ldA[MROWS * NHEADS];
__device__ float g_y  [MROWS * D_INNER];
__device__ float g_y2 [MROWS * D_MODEL];
__device__ float g_y2b[MROWS * D_MODEL];
__device__ float g_S   [BH * NCHUNK * HEADDIM * D_STATE];
__device__ float g_Hs  [BH * NCHUNK * HEADDIM * D_STATE];
__device__ float g_cumL[BH * NCHUNK * QCH];
__device__ float g_eLtot[BH * NCHUNK];
__device__ float g_CB  [2][BC * QCH * QCH];
__device__ int   g_gbar[16];
__device__ __nv_bfloat16 g_wh_in [NB][NPAD_IN * D_MODEL];
__device__ __nv_bfloat16 g_wl_in [NB][NPAD_IN * D_MODEL];
__device__ __nv_bfloat16 g_wh_out[NB][D_MODEL * D_INNER];
__device__ __nv_bfloat16 g_wl_out[NB][D_MODEL * D_INNER];
__device__ __nv_bfloat16 g_wh_hd [NPAD_HD * D_MODEL];
__device__ __nv_bfloat16 g_wl_hd [NPAD_HD * D_MODEL];
__device__ __nv_bfloat16 g_ah[MROWS * D_INNER];
__device__ __nv_bfloat16 g_al[MROWS * D_INNER];

// ---------------- PTX helpers (portable sm_80+ only) ----------------
__device__ __forceinline__ uint32_t smem_u32(const void* p) {
    uint32_t a;
    asm("{ .reg .u64 t; cvta.to.shared.u64 t, %1; cvt.u32.u64 %0, t; }" : "=r"(a) : "l"(p));
    return a;
}
__device__ __forceinline__ void cpa16(uint32_t dst, const void* src) {
    asm volatile("cp.async.cg.shared.global [%0],[%1],16;" :: "r"(dst), "l"(src) : "memory");
}
__device__ __forceinline__ void cpa_commit() {
    asm volatile("cp.async.commit_group;" ::: "memory");
}
template<int N> __device__ __forceinline__ void cpa_wait() {
    asm volatile("cp.async.wait_group %0;" :: "n"(N) : "memory");
}
__device__ __forceinline__ void ldsm4(uint32_t& r0, uint32_t& r1, uint32_t& r2, uint32_t& r3, uint32_t addr) {
    asm volatile("ldmatrix.sync.aligned.m8n8.x4.shared.b16 {%0,%1,%2,%3},[%4];"
                 : "=r"(r0), "=r"(r1), "=r"(r2), "=r"(r3) : "r"(addr));
}
__device__ __forceinline__ void mma16816(float* d, const uint32_t* a, const uint32_t* b) {
    asm volatile(
        "mma.sync.aligned.m16n8k16.row.col.f32.bf16.bf16.f32 "
        "{%0,%1,%2,%3},{%4,%5,%6,%7},{%8,%9},{%0,%1,%2,%3};"
        : "+f"(d[0]), "+f"(d[1]), "+f"(d[2]), "+f"(d[3])
        : "r"(a[0]), "r"(a[1]), "r"(a[2]), "r"(a[3]), "r"(b[0]), "r"(b[1]));
}
__device__ __forceinline__ void split1(float v, __nv_bfloat16& h, __nv_bfloat16& l) {
    __nv_bfloat16 hv = __float2bfloat16(v);
    h = hv;
    l = __float2bfloat16(v - __bfloat162float(hv));
}
__device__ __forceinline__ void grid_barrier(int idx) {
    __syncthreads();
    if (threadIdx.x == 0) {
        __threadfence();
        atomicAdd(&g_gbar[idx], 1);
        while (*((volatile int*)&g_gbar[idx]) < 256) __nanosleep(64);
        __threadfence();
    }
    __syncthreads();
}
// conv4 + silu for one (row m, channel c) of xBC
__device__ __forceinline__ float conv_silu_1(const float* __restrict__ cw,
                                             const float* __restrict__ cb,
                                             int m, int c) {
    int b = m >> 9, l = m & 511;
    float acc = cb[c];
#pragma unroll
    for (int k = 0; k < D_CONV; k++) {
        int ls = l + k - 3;
        if (ls >= 0)
            acc = fmaf(g_zx[(long)((b << 9) + ls) * D_IN_PROJ + D_INNER + c], cw[c * 4 + k], acc);
    }
    return acc / (1.f + __expf(-acc));
}

// ---------------- merged weight splits + embedding, 4 elems/thread ----------------
#define SEG_IN  ((long)NPAD_IN * D_MODEL)
#define SEG_OUT ((long)D_MODEL * D_INNER)
#define WSPLIT_TOTAL (2*SEG_IN + 2*SEG_OUT + SEG_OUT)
#define PREP_TOTAL (WSPLIT_TOTAL + (long)MROWS * D_MODEL)
__global__ void prep_kernel(const float* __restrict__ inw,
                            const float* __restrict__ outw,
                            const float* __restrict__ hw,
                            const int* __restrict__ tokens,
                            const float* __restrict__ emb) {
    long idx = ((long)blockIdx.x * 256 + threadIdx.x) * 4;
    if (blockIdx.x == 0 && threadIdx.x < 16) g_gbar[threadIdx.x] = 0;
    if (idx >= PREP_TOTAL) return;
    if (idx >= WSPLIT_TOTAL) {
        long e = idx - WSPLIT_TOTAL;
        int m = (int)(e >> 9), d = (int)(e & 511);
        float4 v = *(const float4*)(emb + (long)tokens[m] * D_MODEL + d);
        *(float4*)(g_x + e) = v;
        split1(v.x, g_ah[e + 0], g_al[e + 0]);
        split1(v.y, g_ah[e + 1], g_al[e + 1]);
        split1(v.z, g_ah[e + 2], g_al[e + 2]);
        split1(v.w, g_ah[e + 3], g_al[e + 3]);
        return;
    }
    const float* src; __nv_bfloat16 *dh, *dl; int rows, ksh; long off;
    if (idx < 2 * SEG_IN) {
        int layer = idx >= SEG_IN;
        off = idx - (long)layer * SEG_IN;
        src = inw + (long)layer * D_IN_PROJ * D_MODEL;
        dh = g_wh_in[layer]; dl = g_wl_in[layer]; rows = D_IN_PROJ; ksh = 9;
    } else if (idx < 2 * SEG_IN + 2 * SEG_OUT) {
        long r = idx - 2 * SEG_IN;
        int layer = r >= SEG_OUT;
        off = r - (long)layer * SEG_OUT;
        src = outw + (long)layer * SEG_OUT;
        dh = g_wh_out[layer]; dl = g_wl_out[layer]; rows = D_MODEL; ksh = 10;
    } else {
        off = idx - 2 * SEG_IN - 2 * SEG_OUT;
        src = hw; dh = g_wh_hd; dl = g_wl_hd; rows = LABELS; ksh = 9;
    }
    int r = (int)(off >> ksh), c = (int)(off & ((1 << ksh) - 1));
    float4 v = make_float4(0.f, 0.f, 0.f, 0.f);
    if (r < rows) v = *(const float4*)(src + ((long)r << ksh) + c);
    split1(v.x, dh[off + 0], dl[off + 0]);
    split1(v.y, dh[off + 1], dl[off + 1]);
    split1(v.z, dh[off + 2], dl[off + 2]);
    split1(v.w, dh[off + 3], dl[off + 3]);
}

// ---------------- GEMM A: M128xN64 tile, 2-stage, 3 CTAs/SM -> one wave ----------------
#define SROW 80
__global__ __launch_bounds__(256) void mma_gemm_a(
    const __nv_bfloat16* __restrict__ Ah, const __nv_bfloat16* __restrict__ Al,
    const __nv_bfloat16* __restrict__ Wh, const __nv_bfloat16* __restrict__ Wl,
    float* __restrict__ C0, int N, int ld, int kchunks)
{
    constexpr int MT = 128;
    constexpr int BN = 64;
    constexpr int SB = (2 * MT + 2 * BN) * SROW;    // 30720; 2 stages = 61440
    extern __shared__ __align__(16) char dsm[];

    int tid = threadIdx.x;
    int lane = tid & 31, wid = tid >> 5;
    int wm = wid >> 2, wn = wid & 3;
    int rowBase = blockIdx.y * MT;
    int colBase = blockIdx.x * BN;
    uint32_t uDyn = smem_u32(dsm);

    const __nv_bfloat16* Ahp = Ah + (long)rowBase * ld;
    const __nv_bfloat16* Alp = Al + (long)rowBase * ld;
    const __nv_bfloat16* Whp = Wh + (long)colBase * ld;
    const __nv_bfloat16* Wlp = Wl + (long)colBase * ld;

    int r = tid >> 2, s = tid & 3;

    float acc[4][2][4];
#pragma unroll
    for (int i = 0; i < 4; i++)
#pragma unroll
        for (int j = 0; j < 2; j++)
#pragma unroll
            for (int k = 0; k < 4; k++) acc[i][j][k] = 0.f;

    auto load_stage = [&](int cn) {
        uint32_t uS = uDyn + (uint32_t)((cn & 1) * SB);
        long kc = (long)cn * 32;
#pragma unroll
        for (int m0 = 0; m0 < MT; m0 += 64)
            cpa16(uS + (m0 + r) * SROW + s * 16, Ahp + kc + (long)(m0 + r) * ld + s * 8);
#pragma unroll
        for (int m0 = 0; m0 < MT; m0 += 64)
            cpa16(uS + (MT + m0 + r) * SROW + s * 16, Alp + kc + (long)(m0 + r) * ld + s * 8);
        cpa16(uS + (2 * MT + r) * SROW + s * 16, Whp + kc + (long)r * ld + s * 8);
        cpa16(uS + (2 * MT + BN + r) * SROW + s * 16, Wlp + kc + (long)r * ld + s * 8);
    };

    load_stage(0); cpa_commit();

    uint32_t aRowOff = (uint32_t)((wm * 64 + (lane & 15)) * SROW) + ((lane >> 4) ? 16u : 0u);
    uint32_t bRowOff = (uint32_t)((wn * 16 + (((lane >> 4) & 1) << 3) + (lane & 7)) * SROW)
                     + (((lane >> 3) & 1) ? 16u : 0u);

#pragma unroll 1
    for (int c = 0; c < kchunks; c++) {
        if (c + 1 < kchunks) {
            load_stage(c + 1);
            cpa_commit();
            cpa_wait<1>();      // stage c complete; stage c+1 still in flight
        } else {
            cpa_wait<0>();
        }
        __syncthreads();

        uint32_t uS  = uDyn + (uint32_t)((c & 1) * SB);
        uint32_t uAh = uS;
        uint32_t uAl = uS + MT * SROW;
        uint32_t uWh = uS + 2 * MT * SROW;
        uint32_t uWl = uS + (2 * MT + BN) * SROW;
#pragma unroll
        for (int ks = 0; ks < 2; ks++) {
            uint32_t ah[4][4], al[4][4];
#pragma unroll
            for (int mf = 0; mf < 4; mf++) {
                ldsm4(ah[mf][0], ah[mf][1], ah[mf][2], ah[mf][3],
                      uAh + aRowOff + (uint32_t)(mf * 16 * SROW) + (uint32_t)(ks * 32));
                ldsm4(al[mf][0], al[mf][1], al[mf][2], al[mf][3],
                      uAl + aRowOff + (uint32_t)(mf * 16 * SROW) + (uint32_t)(ks * 32));
            }
            uint32_t bh[2][2], bl[2][2];
            {
                uint32_t q0, q1, q2, q3;
                ldsm4(q0, q1, q2, q3, uWh + bRowOff + (uint32_t)(ks * 32));
                bh[0][0] = q0; bh[0][1] = q1; bh[1][0] = q2; bh[1][1] = q3;
                ldsm4(q0, q1, q2, q3, uWl + bRowOff + (uint32_t)(ks * 32));
                bl[0][0] = q0; bl[0][1] = q1; bl[1][0] = q2; bl[1][1] = q3;
            }
#pragma unroll
            for (int mf = 0; mf < 4; mf++)
#pragma unroll
                for (int nf = 0; nf < 2; nf++) {
                    mma16816(acc[mf][nf], ah[mf], bh[nf]);
                    mma16816(acc[mf][nf], ah[mf], bl[nf]);
                    mma16816(acc[mf][nf], al[mf], bh[nf]);
                }
        }
        __syncthreads();
    }

#pragma unroll
    for (int mf = 0; mf < 4; mf++) {
        int rr = rowBase + wm * 64 + mf * 16 + (lane >> 2);
#pragma unroll
        for (int nf = 0; nf < 2; nf++) {
            int cc = colBase + wn * 16 + nf * 8 + (lane & 3) * 2;
            if (cc < N) {
                float* p0 = C0 + (long)rr * N + cc;
                p0[0] = acc[mf][nf][0];
                if (cc + 1 < N) p0[1] = acc[mf][nf][1];
                float* p1 = C0 + (long)(rr + 8) * N + cc;
                p1[0] = acc[mf][nf][2];
                if (cc + 1 < N) p1[1] = acc[mf][nf][3];
            }
        }
    }
}

// ---------------- GEMM B: M64xN64, 4-stage pair pipeline (out_proj/head) ----------------
__global__ __launch_bounds__(256) void mma_gemm_b(
    const __nv_bfloat16* __restrict__ Ah, const __nv_bfloat16* __restrict__ Al,
    const __nv_bfloat16* __restrict__ Wh, const __nv_bfloat16* __restrict__ Wl,
    const float* __restrict__ bias, float* __restrict__ C0, float* __restrict__ C1,
    int N, int ld, int kchunks, int kzOff)
{
    constexpr int MT = 64;
    constexpr int BN = 64;
    constexpr int SB = (2 * MT + 2 * BN) * SROW;   // 20480
    extern __shared__ __align__(16) char dsm[];

    int tid = threadIdx.x;
    int lane = tid & 31, wid = tid >> 5;
    int wm = wid >> 2, wn = wid & 3;
    int rowBase = blockIdx.y * MT;
    int colBase = blockIdx.x * BN;
    int z = blockIdx.z;
    float* C = z ? C1 : C0;
    uint32_t uDyn = smem_u32(dsm);

    const __nv_bfloat16* Ahp = Ah + (long)rowBase * ld + (long)z * kzOff;
    const __nv_bfloat16* Alp = Al + (long)rowBase * ld + (long)z * kzOff;
    const __nv_bfloat16* Whp = Wh + (long)colBase * ld + (long)z * kzOff;
    const __nv_bfloat16* Wlp = Wl + (long)colBase * ld + (long)z * kzOff;

    int r = tid >> 2, s = tid & 3;

    float acc[2][2][4];
#pragma unroll
    for (int i = 0; i < 2; i++)
#pragma unroll
        for (int j = 0; j < 2; j++)
#pragma unroll
            for (int k = 0; k < 4; k++) acc[i][j][k] = 0.f;

    auto load_stage = [&](int cn) {
        uint32_t uS = uDyn + (uint32_t)((cn & 3) * SB);
        long kc = (long)cn * 32;
        cpa16(uS + r * SROW + s * 16,                 Ahp + kc + (long)r * ld + s * 8);
        cpa16(uS + (MT + r) * SROW + s * 16,          Alp + kc + (long)r * ld + s * 8);
        cpa16(uS + (2 * MT + r) * SROW + s * 16,      Whp + kc + (long)r * ld + s * 8);
        cpa16(uS + (2 * MT + BN + r) * SROW + s * 16, Wlp + kc + (long)r * ld + s * 8);
    };

    load_stage(0); cpa_commit();
    load_stage(1); cpa_commit();

    uint32_t aRowOff = (uint32_t)((wm * 32 + (lane & 15)) * SROW) + ((lane >> 4) ? 16u : 0u);
    uint32_t bRowOff = (uint32_t)((wn * 16 + (((lane >> 4) & 1) << 3) + (lane & 7)) * SROW)
                     + (((lane >> 3) & 1) ? 16u : 0u);

    int pairs = kchunks >> 1;
#pragma unroll 1
    for (int p = 0; p < pairs; p++) {
        cpa_wait<0>();
        __syncthreads();
        int cn = 2 * p + 2;
        if (cn < kchunks) {
            load_stage(cn);     cpa_commit();
            load_stage(cn + 1); cpa_commit();
        }
#pragma unroll
        for (int sub = 0; sub < 4; sub++) {
            int cc = 2 * p + (sub >> 1);
            int ks = sub & 1;
            uint32_t uS  = uDyn + (uint32_t)((cc & 3) * SB);
            uint32_t off = (uint32_t)(ks * 32);
            uint32_t ah[2][4], al[2][4];
#pragma unroll
            for (int mf = 0; mf < 2; mf++) {
                ldsm4(ah[mf][0], ah[mf][1], ah[mf][2], ah[mf][3],
                      uS + aRowOff + (uint32_t)(mf * 16 * SROW) + off);
                ldsm4(al[mf][0], al[mf][1], al[mf][2], al[mf][3],
                      uS + MT * SROW + aRowOff + (uint32_t)(mf * 16 * SROW) + off);
            }
            uint32_t bh[2][2], bl[2][2];
            {
                uint32_t q0, q1, q2, q3;
                ldsm4(q0, q1, q2, q3, uS + 2 * MT * SROW + bRowOff + off);
                bh[0][0] = q0; bh[0][1] = q1; bh[1][0] = q2; bh[1][1] = q3;
                ldsm4(q0, q1, q2, q3, uS + (2 * MT + BN) * SROW + bRowOff + off);
                bl[0][0] = q0; bl[0][1] = q1; bl[1][0] = q2; bl[1][1] = q3;
            }
#pragma unroll
            for (int mf = 0; mf < 2; mf++)
#pragma unroll
                for (int nf = 0; nf < 2; nf++) {
                    mma16816(acc[mf][nf], ah[mf], bh[nf]);
                    mma16816(acc[mf][nf], ah[mf], bl[nf]);
                    mma16816(acc[mf][nf], al[mf], bh[nf]);
                }
        }
    }

#pragma unroll
    for (int mf = 0; mf < 2; mf++) {
        int rr = rowBase + wm * 32 + mf * 16 + (lane >> 2);
#pragma unroll
        for (int nf = 0; nf < 2; nf++) {
            int cc = colBase + wn * 16 + nf * 8 + (lane & 3) * 2;
            if (cc < N) {
                float b0 = bias ? bias[cc] : 0.f;
                float b1 = bias ? ((cc + 1 < N) ? bias[cc + 1] : 0.f) : 0.f;
                float* p0 = C + (long)rr * N + cc;
                p0[0] = acc[mf][nf][0] + b0;
                if (cc + 1 < N) p0[1] = acc[mf][nf][1] + b1;
                float* p1 = C + (long)(rr + 8) * N + cc;
                p1[0] = acc[mf][nf][2] + b0;
                if (cc + 1 < N) p1[1] = acc[mf][nf][3] + b1;
            }
        }
    }
}

// ---------------- FUSED mid-section (256 blocks, 4 barriers) ----------------
#define SH_BYTES 35840
#define CONVXQ (MROWS * D_INNER / 4)    // 262144 (x-columns only)
#define DTQ    (MROWS * NHEADS / 4)     // 4096
__global__ __launch_bounds__(256, 2) void fused_mid(
    const float* __restrict__ cw, const float* __restrict__ cb,
    const float* __restrict__ dtb, const float* __restrict__ A_log,
    const float* __restrict__ Dv, const float* __restrict__ rw,
    int barBase)
{
    __shared__ __align__(16) char sh[SH_BYTES];
    int bb = blockIdx.x;
    int tid = threadIdx.x;
    int lane = tid & 31;

    // ===== Phase A/B merged =====
    for (int q = bb * 256 + tid; q < CONVXQ + DTQ; q += 65536) {
        if (q < CONVXQ) {
            int m = q >> 8;
            int c = (q & 255) * 4;
            int b = m >> 9, l = m & 511;
            float4 a = *(const float4*)(cb + c);
            float4 w0 = *(const float4*)(cw + (c + 0) * 4);
            float4 w1 = *(const float4*)(cw + (c + 1) * 4);
            float4 w2 = *(const float4*)(cw + (c + 2) * 4);
            float4 w3 = *(const float4*)(cw + (c + 3) * 4);
            float wa0[4] = {w0.x, w0.y, w0.z, w0.w};
            float wa1[4] = {w1.x, w1.y, w1.z, w1.w};
            float wa2[4] = {w2.x, w2.y, w2.z, w2.w};
            float wa3[4] = {w3.x, w3.y, w3.z, w3.w};
#pragma unroll
            for (int k = 0; k < 4; k++) {
                int ls = l + k - 3;
                if (ls >= 0) {
                    float4 v = *(const float4*)(g_zx + (long)((b << 9) + ls) * D_IN_PROJ + D_INNER + c);
                    a.x = fmaf(v.x, wa0[k], a.x);
                    a.y = fmaf(v.y, wa1[k], a.y);
                    a.z = fmaf(v.z, wa2[k], a.z);
                    a.w = fmaf(v.w, wa3[k], a.w);
                }
            }
            a.x = a.x / (1.f + __expf(-a.x));
            a.y = a.y / (1.f + __expf(-a.y));
            a.z = a.z / (1.f + __expf(-a.z));
            a.w = a.w / (1.f + __expf(-a.w));
            *(float4*)(g_xbc + (long)m * CONV_DIM + c) = a;
        } else {
            int rq = q - CONVXQ;
            int m = rq >> 2, h = (rq & 3) * 4;
#pragma unroll
            for (int j = 0; j < 4; j++) {
                float v = g_zx[(long)m * D_IN_PROJ + D_INNER + CONV_DIM + h + j] + dtb[h + j];
                float dt = (v > 20.f) ? v : log1pf(expf(v));
                float A = -expf(A_log[h + j]);
                g_dt[m * NHEADS + h + j] = dt;
                g_ldA[m * NHEADS + h + j] = dt * A;
            }
        }
    }

    {
        float (*sB64)[65] = (float(*)[65])sh;
        float (*sC8)[65]  = (float(*)[65])(sh + 64 * 65 * 4);
        int cbIdx = bb & 15;
        int half  = (bb >> 4) & 1;
        int slice = bb >> 5;
        int b = cbIdx >> 3, c = cbIdx & 7;
        int mBase = b * SEQ + c * QCH;
        for (int i = tid; i < 64 * 64; i += 256) {
            int s2 = i >> 6, n = i & 63;
            int ch = D_INNER + half * 64 + n;
            int m = mBase + s2;
            float v = conv_silu_1(cw, cb, m, ch);
            sB64[s2][n] = v;
            g_xbc[(long)m * CONV_DIM + ch] = v;
        }
        for (int i = tid; i < 8 * 64; i += 256) {
            int t = i >> 6, n = i & 63;
            int ch = D_INNER + D_STATE + half * 64 + n;
            int m = mBase + slice * 8 + t;
            float v = conv_silu_1(cw, cb, m, ch);
            sC8[t][n] = v;
            g_xbc[(long)m * CONV_DIM + ch] = v;
        }
        __syncthreads();
        int t = tid >> 5;
        long base = (long)cbIdx * (QCH * QCH);
#pragma unroll
        for (int ss = 0; ss < 2; ss++) {
            int s2 = lane + ss * 32;
            float acc = 0.f;
#pragma unroll
            for (int n = 0; n < 64; n++) acc = fmaf(sC8[t][n], sB64[s2][n], acc);
            g_CB[half][base + (slice * 8 + t) * 64 + s2] = acc;
        }
    }
    grid_barrier(barBase + 0);

    // ===== Phase C: cumsum L, G, y_local, S =====
    {
        float (*sA)[68] = (float(*)[68])sh;
        float (*sG)[68] = (float(*)[68])(sh + 64 * 68 * 4);
        float* sL  = (float*)(sh + 2 * 64 * 68 * 4);
        float* sDt = sL + 64;
        int c = bb & 7, bh = bb >> 3;
        int b = bh >> 4, h = bh & 15;
        int mBase = b * SEQ + c * QCH;
        int ty = tid >> 4, tx = tid & 15;
        int t4 = tid >> 2, j16 = (tid & 3) * 16;
        {
            const float* src = g_xbc + (long)(mBase + t4) * CONV_DIM + h * HEADDIM + j16;
#pragma unroll
            for (int q = 0; q < 4; q++) {
                float4 v = *(const float4*)(src + q * 4);
                sA[t4][j16 + q * 4 + 0] = v.x; sA[t4][j16 + q * 4 + 1] = v.y;
                sA[t4][j16 + q * 4 + 2] = v.z; sA[t4][j16 + q * 4 + 3] = v.w;
            }
        }
        if (tid < 64) {
            sDt[tid] = g_dt[(mBase + tid) * NHEADS + h];
            sL[tid]  = g_ldA[(mBase + tid) * NHEADS + h];
        }
        __syncthreads();
        if (tid < 64) {
            float v = sL[tid];
#pragma unroll
            for (int o = 1; o < 32; o <<= 1) {
                float n = __shfl_up_sync(0xffffffffu, v, o);
                if (lane >= o) v += n;
            }
            sL[tid] = v;
        }
        __syncthreads();
        if (tid >= 32 && tid < 64) sL[tid] += sL[31];
        __syncthreads();
        if (tid < 64) {
            g_cumL[bb * QCH + tid] = sL[tid];
            if (tid == 63) g_eLtot[bb] = __expf(sL[63]);
        }
        long cbbase = (long)((b << 3) + c) * (QCH * QCH);
#pragma unroll
        for (int i = 0; i < 4; i++) {
            int t = ty * 4 + i;
#pragma unroll
            for (int j = 0; j < 4; j++) {
                int s2 = tx * 4 + j;
                float g = 0.f;
                if (s2 <= t) {
                    float raw = g_CB[0][cbbase + t * 64 + s2] + g_CB[1][cbbase + t * 64 + s2];
                    g = raw * __expf(sL[t] - sL[s2]) * sDt[s2];
                }
                sG[t][s2] = g;
            }
        }
        __syncthreads();
        {
            float yv[4][4];
#pragma unroll
            for (int i = 0; i < 4; i++)
#pragma unroll
                for (int j = 0; j < 4; j++) yv[i][j] = 0.f;
#pragma unroll 4
            for (int s2 = 0; s2 < 64; s2++) {
                float av[4];
#pragma unroll
                for (int i = 0; i < 4; i++) av[i] = sG[ty * 4 + i][s2];
                float4 b4 = *(const float4*)&sA[s2][tx * 4];
                float bv[4] = {b4.x, b4.y, b4.z, b4.w};
#pragma unroll
                for (int i = 0; i < 4; i++)
#pragma unroll
                    for (int j = 0; j < 4; j++) yv[i][j] = fmaf(av[i], bv[j], yv[i][j]);
            }
            float Dval = Dv[h];
#pragma unroll
            for (int i = 0; i < 4; i++) {
                int t = ty * 4 + i;
#pragma unroll
                for (int j = 0; j < 4; j++) {
                    int p = tx * 4 + j;
                    g_y[(long)(mBase + t) * D_INNER + h * HEADDIM + p] = yv[i][j] + Dval * sA[t][p];
                }
            }
        }
        __syncthreads();
        {
            float w = __expf(sL[63] - sL[t4]) * sDt[t4];
#pragma unroll
            for (int q = 0; q < 16; q++) sA[t4][j16 + q] *= w;
        }
        long sbase = (long)bb * (HEADDIM * D_STATE);
#pragma unroll 1
        for (int nh = 0; nh < 2; nh++) {
            __syncthreads();
            {
                const float* bsrc = g_xbc + (long)(mBase + t4) * CONV_DIM + D_INNER + nh * 64 + j16;
#pragma unroll
                for (int q = 0; q < 4; q++) {
                    float4 v = *(const float4*)(bsrc + q * 4);
                    sG[t4][j16 + q * 4 + 0] = v.x; sG[t4][j16 + q * 4 + 1] = v.y;
                    sG[t4][j16 + q * 4 + 2] = v.z; sG[t4][j16 + q * 4 + 3] = v.w;
                }
            }
            __syncthreads();
            float sv[4][4];
#pragma unroll
            for (int i = 0; i < 4; i++)
#pragma unroll
                for (int j = 0; j < 4; j++) sv[i][j] = 0.f;
#pragma unroll 4
            for (int t = 0; t < 64; t++) {
                float4 a4 = *(const float4*)&sA[t][ty * 4];
                float4 b4 = *(const float4*)&sG[t][tx * 4];
                float av[4] = {a4.x, a4.y, a4.z, a4.w};
                float bv[4] = {b4.x, b4.y, b4.z, b4.w};
#pragma unroll
                for (int i = 0; i < 4; i++)
#pragma unroll
                    for (int j = 0; j < 4; j++) sv[i][j] = fmaf(av[i], bv[j], sv[i][j]);
            }
#pragma unroll
            for (int i = 0; i < 4; i++) {
                int p = ty * 4 + i;
#pragma unroll
                for (int j = 0; j < 4; j++)
                    g_S[sbase + (long)p * D_STATE + nh * 64 + tx * 4 + j] = sv[i][j];
            }
        }
    }
    grid_barrier(barBase + 1);

    // ===== Phase D: inter-chunk recurrence, 256-wide =====
    {
        int bh = bb >> 3, slice = bb & 7;
        float H[4];
#pragma unroll
        for (int k = 0; k < 4; k++) H[k] = 0.f;
#pragma unroll 1
        for (int c = 0; c < NCHUNK; c++) {
            long base = ((long)(bh * NCHUNK + c)) * HEADDIM * D_STATE + slice * 1024;
            float el = g_eLtot[bh * NCHUNK + c];
#pragma unroll
            for (int k = 0; k < 4; k++) {
                long e = base + tid + k * 256;
                g_Hs[e] = H[k];
                H[k] = el * H[k] + g_S[e];
            }
        }
    }
    grid_barrier(barBase + 2);

    // ===== Phase E: y += exp(L_t) * C_t . H_start =====
    {
        float (*sTa)[72] = (float(*)[72])sh;
        float (*sTh)[72] = (float(*)[72])(sh + 16 * 72 * 4);
        float* sEL = (float*)(sh + 2 * 16 * 72 * 4);
        int c = bb & 7, bh = bb >> 3;
        int b = bh >> 4, h = bh & 15;
        int mBase = b * SEQ + c * QCH;
        int ty = tid >> 4, tx = tid & 15;
        if (tid < 64) sEL[tid] = __expf(g_cumL[bb * QCH + tid]);

        float acc[4][4];
#pragma unroll
        for (int i = 0; i < 4; i++)
#pragma unroll
            for (int j = 0; j < 4; j++) acc[i][j] = 0.f;

        long hbase = (long)bb * (HEADDIM * D_STATE);
#pragma unroll 1
        for (int n0 = 0; n0 < D_STATE; n0 += 16) {
            __syncthreads();
            {
                int t = tid >> 2, jj = (tid & 3) * 4;
                float4 cv = *(const float4*)(g_xbc + (long)(mBase + t) * CONV_DIM + D_INNER + D_STATE + n0 + jj);
                sTa[jj + 0][t] = cv.x; sTa[jj + 1][t] = cv.y; sTa[jj + 2][t] = cv.z; sTa[jj + 3][t] = cv.w;
                float4 hv = *(const float4*)(g_Hs + hbase + (long)t * D_STATE + n0 + jj);
                sTh[jj + 0][t] = hv.x; sTh[jj + 1][t] = hv.y; sTh[jj + 2][t] = hv.z; sTh[jj + 3][t] = hv.w;
            }
            __syncthreads();
#pragma unroll
            for (int nn = 0; nn < 16; nn++) {
                float4 a4 = *(const float4*)&sTa[nn][ty * 4];
                float4 b4 = *(const float4*)&sTh[nn][tx * 4];
                float av[4] = {a4.x, a4.y, a4.z, a4.w};
                float bv[4] = {b4.x, b4.y, b4.z, b4.w};
#pragma unroll
                for (int i = 0; i < 4; i++)
#pragma unroll
                    for (int j = 0; j < 4; j++) acc[i][j] = fmaf(av[i], bv[j], acc[i][j]);
            }
        }
#pragma unroll
        for (int i = 0; i < 4; i++) {
            int t = ty * 4 + i;
            float e = sEL[t];
#pragma unroll
            for (int j = 0; j < 4; j++) {
                int p = tx * 4 + j;
                long idx = (long)(mBase + t) * D_INNER + h * HEADDIM + p;
                g_y[idx] += e * acc[i][j];
            }
        }
    }
    grid_barrier(barBase + 3);

    // ===== Phase F: gate + RMSNorm + split =====
    {
        float* red = (float*)sh;
#pragma unroll 1
        for (int rr = 0; rr < 4; rr++) {
            int m = bb * 4 + rr;
            float vals[4];
            float ss = 0.f;
#pragma unroll
            for (int i = 0; i < 4; i++) {
                int c = tid + i * 256;
                float z = g_zx[(long)m * D_IN_PROJ + c];
                float gate = z / (1.f + __expf(-z));
                float v = g_y[(long)m * D_INNER + c] * gate;
                vals[i] = v;
                ss = fmaf(v, v, ss);
            }
#pragma unroll
            for (int o = 16; o; o >>= 1) ss += __shfl_xor_sync(0xffffffffu, ss, o);
            __syncthreads();
            if (lane == 0) red[tid >> 5] = ss;
            __syncthreads();
            float tot = 0.f;
#pragma unroll
            for (int i = 0; i < 8; i++) tot += red[i];
            float rs = rsqrtf(tot * (1.f / D_INNER) + 1e-5f);
#pragma unroll
            for (int i = 0; i < 4; i++) {
                int c = tid + i * 256;
                float v = vals[i] * rs * rw[c];
                split1(v, g_ah[(long)m * D_INNER + c], g_al[(long)m * D_INNER + c]);
            }
        }
    }
}

// ---------------- residual + LayerNorm + split (4 rows/block) ----------------
__global__ __launch_bounds__(256) void res_ln_split(const float* __restrict__ lw,
                                                    const float* __restrict__ lb) {
    int t = threadIdx.x;
    __shared__ float red[8];
#pragma unroll 1
    for (int rr = 0; rr < 4; rr++) {
        int m = blockIdx.x * 4 + rr;
        long base = (long)m * D_MODEL;
        float v0 = g_y2[base + t]       + g_y2b[base + t]       + g_x[base + t];
        float v1 = g_y2[base + t + 256] + g_y2b[base + t + 256] + g_x[base + t + 256];
        float s = v0 + v1;
#pragma unroll
        for (int o = 16; o; o >>= 1) s += __shfl_xor_sync(0xffffffffu, s, o);
        __syncthreads();
        if ((t & 31) == 0) red[t >> 5] = s;
        __syncthreads();
        float tot = 0.f;
#pragma unroll
        for (int i = 0; i < 8; i++) tot += red[i];
        float mu = tot * (1.f / D_MODEL);
        float c0 = v0 - mu, c1 = v1 - mu;
        float ss = c0 * c0 + c1 * c1;
#pragma unroll
        for (int o = 16; o; o >>= 1) ss += __shfl_xor_sync(0xffffffffu, ss, o);
        __syncthreads();
        if ((t & 31) == 0) red[t >> 5] = ss;
        __syncthreads();
        float vtot = 0.f;
#pragma unroll
        for (int i = 0; i < 8; i++) vtot += red[i];
        float rs = rsqrtf(vtot * (1.f / D_MODEL) + 1e-5f);
        float o0 = c0 * rs * lw[t]       + lb[t];
        float o1 = c1 * rs * lw[t + 256] + lb[t + 256];
        g_x[base + t]       = o0;
        g_x[base + t + 256] = o1;
        split1(o0, g_ah[base + t],       g_al[base + t]);
        split1(o1, g_ah[base + t + 256], g_al[base + t + 256]);
    }
}

// ---------------- launch ----------------
#define DSMA (2 * (256 + 128) * SROW)   // 61440 -> 3 CTAs/SM, one wave for 304 CTAs
#define DSMB (4 * (128 + 128) * SROW)   // 81920
extern "C" void kernel_launch(void* const* d_in, const int* in_sizes, int n_in,
                              void* d_out, int out_size) {
    const int*   tokens    = (const int*)  d_in[0];
    const float* embedding = (const float*)d_in[1];
    const float* in_proj_w = (const float*)d_in[2];
    const float* conv_w    = (const float*)d_in[3];
    const float* conv_b    = (const float*)d_in[4];
    const float* dt_bias   = (const float*)d_in[5];
    const float* A_log     = (const float*)d_in[6];
    const float* Dv        = (const float*)d_in[7];
    const float* rms_w     = (const float*)d_in[8];
    const float* out_proj_w= (const float*)d_in[9];
    const float* ln_w      = (const float*)d_in[10];
    const float* ln_b      = (const float*)d_in[11];
    const float* head_w    = (const float*)d_in[12];
    const float* head_b    = (const float*)d_in[13];
    float* out = (float*)d_out;

    cudaFuncSetAttribute(mma_gemm_a, cudaFuncAttributeMaxDynamicSharedMemorySize, DSMA);
    cudaFuncSetAttribute(mma_gemm_b, cudaFuncAttributeMaxDynamicSharedMemorySize, DSMB);

    void *p_zx, *p_y2, *p_y2b, *p_ah, *p_al;
    void *p_whin, *p_wlin, *p_whout, *p_wlout, *p_whhd, *p_wlhd;
    cudaGetSymbolAddress(&p_zx, g_zx);
    cudaGetSymbolAddress(&p_y2, g_y2);
    cudaGetSymbolAddress(&p_y2b, g_y2b);
    cudaGetSymbolAddress(&p_ah, g_ah);
    cudaGetSymbolAddress(&p_al, g_al);
    cudaGetSymbolAddress(&p_whin,  g_wh_in);
    cudaGetSymbolAddress(&p_wlin,  g_wl_in);
    cudaGetSymbolAddress(&p_whout, g_wh_out);
    cudaGetSymbolAddress(&p_wlout, g_wl_out);
    cudaGetSymbolAddress(&p_whhd,  g_wh_hd);
    cudaGetSymbolAddress(&p_wlhd,  g_wl_hd);
    float* dzx  = (float*)p_zx;
    float* dy2  = (float*)p_y2;
    float* dy2b = (float*)p_y2b;
    __nv_bfloat16* ah = (__nv_bfloat16*)p_ah;
    __nv_bfloat16* al = (__nv_bfloat16*)p_al;
    __nv_bfloat16* whin  = (__nv_bfloat16*)p_whin;
    __nv_bfloat16* wlin  = (__nv_bfloat16*)p_wlin;
    __nv_bfloat16* whout = (__nv_bfloat16*)p_whout;
    __nv_bfloat16* wlout = (__nv_bfloat16*)p_wlout;
    __nv_bfloat16* whhd  = (__nv_bfloat16*)p_whhd;
    __nv_bfloat16* wlhd  = (__nv_bfloat16*)p_wlhd;

    prep_kernel<<<(int)((PREP_TOTAL / 4 + 255) / 256), 256>>>(
        in_proj_w, out_proj_w, head_w, tokens, embedding);

    for (int i = 0; i < NB; i++) {
        // in_proj: M128xN64, 2-stage, 304 CTAs in ONE wave (3 CTAs/SM)
        mma_gemm_a<<<dim3(NPAD_IN / 64, MROWS / 128, 1), 256, DSMA>>>(
            ah, al, whin + (long)i * NPAD_IN * D_MODEL, wlin + (long)i * NPAD_IN * D_MODEL,
            dzx, D_IN_PROJ, D_MODEL, D_MODEL / 32);
        fused_mid<<<256, 256>>>(
            conv_w + (long)i * CONV_DIM * D_CONV, conv_b + (long)i * CONV_DIM,
            dt_bias + i * NHEADS, A_log + i * NHEADS,
            Dv + i * NHEADS, rms_w + (long)i * D_INNER, i * 4);
        mma_gemm_b<<<dim3(D_MODEL / 64, MROWS / 64, 2), 256, DSMB>>>(
            ah, al, whout + (long)i * D_MODEL * D_INNER, wlout + (long)i * D_MODEL * D_INNER,
            nullptr, dy2, dy2b, D_MODEL, D_INNER, 512 / 32, 512);
        res_ln_split<<<MROWS / 4, 256>>>(ln_w + i * D_MODEL, ln_b + i * D_MODEL);
    }

    mma_gemm_b<<<dim3(NPAD_HD / 64, MROWS / 64, 1), 256, DSMB>>>(
        ah, al, whhd, wlhd, head_b, out, nullptr, LABELS, D_MODEL, D_MODEL / 32, 0);
}

// round 15
// speedup vs baseline: 1.0038x; 1.0038x over previous
#include <cuda_runtime.h>
#include <cuda_bf16.h>
#include <math.h>
#include <stdint.h>

// ---------------- problem constants ----------------
#define NB        2
#define D_MODEL   512
#define D_STATE   128
#define D_CONV    4
#define HEADDIM   64
#define D_INNER   1024
#define NHEADS    16
#define CONV_DIM  1280
#define D_IN_PROJ 2320
#define NPAD_IN   2432
#define LABELS    1000
#define NPAD_HD   1024
#define BATCH     2
#define SEQ       512
#define MROWS     (BATCH*SEQ)
#define QCH       64
#define NCHUNK    (SEQ/QCH)     // 8
#define BH        (BATCH*NHEADS)// 32
#define BC        (BATCH*NCHUNK)// 16

// ---------------- scratch ----------------
__device__ float g_x  [MROWS * D_MODEL];
__device__ float g_zx [MROWS * D_IN_PROJ];
__device__ float g_xbc[MROWS * CONV_DIM];
__device__ float g_dt [MROWS * NHEADS];
__device__ float g_ldA[MROWS * NHEADS];
__device__ float g_y  [MROWS * D_INNER];
__device__ float g_y2 [MROWS * D_MODEL];
__device__ float g_y2b[MROWS * D_MODEL];
__device__ float g_S   [BH * NCHUNK * HEADDIM * D_STATE];
__device__ float g_Hs  [BH * NCHUNK * HEADDIM * D_STATE];
__device__ float g_cumL[BH * NCHUNK * QCH];
__device__ float g_eLtot[BH * NCHUNK];
__device__ float g_CB  [2][BC * QCH * QCH];
__device__ int   g_gbar[16];
__device__ __nv_bfloat16 g_wh_in [NB][NPAD_IN * D_MODEL];
__device__ __nv_bfloat16 g_wl_in [NB][NPAD_IN * D_MODEL];
__device__ __nv_bfloat16 g_wh_out[NB][D_MODEL * D_INNER];
__device__ __nv_bfloat16 g_wl_out[NB][D_MODEL * D_INNER];
__device__ __nv_bfloat16 g_wh_hd [NPAD_HD * D_MODEL];
__device__ __nv_bfloat16 g_wl_hd [NPAD_HD * D_MODEL];
__device__ __nv_bfloat16 g_ah[MROWS * D_INNER];
__device__ __nv_bfloat16 g_al[MROWS * D_INNER];

// ---------------- PTX helpers (portable sm_80+ only) ----------------
__device__ __forceinline__ uint32_t smem_u32(const void* p) {
    uint32_t a;
    asm("{ .reg .u64 t; cvta.to.shared.u64 t, %1; cvt.u32.u64 %0, t; }" : "=r"(a) : "l"(p));
    return a;
}
__device__ __forceinline__ void cpa16(uint32_t dst, const void* src) {
    asm volatile("cp.async.cg.shared.global [%0],[%1],16;" :: "r"(dst), "l"(src) : "memory");
}
__device__ __forceinline__ void cpa_commit() {
    asm volatile("cp.async.commit_group;" ::: "memory");
}
template<int N> __device__ __forceinline__ void cpa_wait() {
    asm volatile("cp.async.wait_group %0;" :: "n"(N) : "memory");
}
__device__ __forceinline__ void ldsm4(uint32_t& r0, uint32_t& r1, uint32_t& r2, uint32_t& r3, uint32_t addr) {
    asm volatile("ldmatrix.sync.aligned.m8n8.x4.shared.b16 {%0,%1,%2,%3},[%4];"
                 : "=r"(r0), "=r"(r1), "=r"(r2), "=r"(r3) : "r"(addr));
}
__device__ __forceinline__ void mma16816(float* d, const uint32_t* a, const uint32_t* b) {
    asm volatile(
        "mma.sync.aligned.m16n8k16.row.col.f32.bf16.bf16.f32 "
        "{%0,%1,%2,%3},{%4,%5,%6,%7},{%8,%9},{%0,%1,%2,%3};"
        : "+f"(d[0]), "+f"(d[1]), "+f"(d[2]), "+f"(d[3])
        : "r"(a[0]), "r"(a[1]), "r"(a[2]), "r"(a[3]), "r"(b[0]), "r"(b[1]));
}
__device__ __forceinline__ void split1(float v, __nv_bfloat16& h, __nv_bfloat16& l) {
    __nv_bfloat16 hv = __float2bfloat16(v);
    h = hv;
    l = __float2bfloat16(v - __bfloat162float(hv));
}
__device__ __forceinline__ void grid_barrier(int idx) {
    __syncthreads();
    if (threadIdx.x == 0) {
        __threadfence();
        atomicAdd(&g_gbar[idx], 1);
        while (*((volatile int*)&g_gbar[idx]) < 256) __nanosleep(64);
        __threadfence();
    }
    __syncthreads();
}
// conv4 + silu for one (row m, channel c) of xBC
__device__ __forceinline__ float conv_silu_1(const float* __restrict__ cw,
                                             const float* __restrict__ cb,
                                             int m, int c) {
    int b = m >> 9, l = m & 511;
    float acc = cb[c];
#pragma unroll
    for (int k = 0; k < D_CONV; k++) {
        int ls = l + k - 3;
        if (ls >= 0)
            acc = fmaf(g_zx[(long)((b << 9) + ls) * D_IN_PROJ + D_INNER + c], cw[c * 4 + k], acc);
    }
    return acc / (1.f + __expf(-acc));
}

// ---------------- merged weight splits + embedding, 4 elems/thread ----------------
#define SEG_IN  ((long)NPAD_IN * D_MODEL)
#define SEG_OUT ((long)D_MODEL * D_INNER)
#define WSPLIT_TOTAL (2*SEG_IN + 2*SEG_OUT + SEG_OUT)
#define PREP_TOTAL (WSPLIT_TOTAL + (long)MROWS * D_MODEL)
__global__ void prep_kernel(const float* __restrict__ inw,
                            const float* __restrict__ outw,
                            const float* __restrict__ hw,
                            const int* __restrict__ tokens,
                            const float* __restrict__ emb) {
    long idx = ((long)blockIdx.x * 256 + threadIdx.x) * 4;
    if (blockIdx.x == 0 && threadIdx.x < 16) g_gbar[threadIdx.x] = 0;
    if (idx >= PREP_TOTAL) return;
    if (idx >= WSPLIT_TOTAL) {
        long e = idx - WSPLIT_TOTAL;
        int m = (int)(e >> 9), d = (int)(e & 511);
        float4 v = *(const float4*)(emb + (long)tokens[m] * D_MODEL + d);
        *(float4*)(g_x + e) = v;
        split1(v.x, g_ah[e + 0], g_al[e + 0]);
        split1(v.y, g_ah[e + 1], g_al[e + 1]);
        split1(v.z, g_ah[e + 2], g_al[e + 2]);
        split1(v.w, g_ah[e + 3], g_al[e + 3]);
        return;
    }
    const float* src; __nv_bfloat16 *dh, *dl; int rows, ksh; long off;
    if (idx < 2 * SEG_IN) {
        int layer = idx >= SEG_IN;
        off = idx - (long)layer * SEG_IN;
        src = inw + (long)layer * D_IN_PROJ * D_MODEL;
        dh = g_wh_in[layer]; dl = g_wl_in[layer]; rows = D_IN_PROJ; ksh = 9;
    } else if (idx < 2 * SEG_IN + 2 * SEG_OUT) {
        long r = idx - 2 * SEG_IN;
        int layer = r >= SEG_OUT;
        off = r - (long)layer * SEG_OUT;
        src = outw + (long)layer * SEG_OUT;
        dh = g_wh_out[layer]; dl = g_wl_out[layer]; rows = D_MODEL; ksh = 10;
    } else {
        off = idx - 2 * SEG_IN - 2 * SEG_OUT;
        src = hw; dh = g_wh_hd; dl = g_wl_hd; rows = LABELS; ksh = 9;
    }
    int r = (int)(off >> ksh), c = (int)(off & ((1 << ksh) - 1));
    float4 v = make_float4(0.f, 0.f, 0.f, 0.f);
    if (r < rows) v = *(const float4*)(src + ((long)r << ksh) + c);
    split1(v.x, dh[off + 0], dl[off + 0]);
    split1(v.y, dh[off + 1], dl[off + 1]);
    split1(v.z, dh[off + 2], dl[off + 2]);
    split1(v.w, dh[off + 3], dl[off + 3]);
}

// ---------------- GEMM A: M128xN64 tile, 3-stage (for in_proj) ----------------
#define SROW 80
__global__ __launch_bounds__(256) void mma_gemm_a(
    const __nv_bfloat16* __restrict__ Ah, const __nv_bfloat16* __restrict__ Al,
    const __nv_bfloat16* __restrict__ Wh, const __nv_bfloat16* __restrict__ Wl,
    float* __restrict__ C0, int N, int ld, int kchunks)
{
    constexpr int MT = 128;
    constexpr int BN = 64;
    constexpr int SB = (2 * MT + 2 * BN) * SROW;
    extern __shared__ __align__(16) char dsm[];

    int tid = threadIdx.x;
    int lane = tid & 31, wid = tid >> 5;
    int wm = wid >> 2, wn = wid & 3;
    int rowBase = blockIdx.y * MT;
    int colBase = blockIdx.x * BN;
    uint32_t uDyn = smem_u32(dsm);

    const __nv_bfloat16* Ahp = Ah + (long)rowBase * ld;
    const __nv_bfloat16* Alp = Al + (long)rowBase * ld;
    const __nv_bfloat16* Whp = Wh + (long)colBase * ld;
    const __nv_bfloat16* Wlp = Wl + (long)colBase * ld;

    int r = tid >> 2, s = tid & 3;

    float acc[4][2][4];
#pragma unroll
    for (int i = 0; i < 4; i++)
#pragma unroll
        for (int j = 0; j < 2; j++)
#pragma unroll
            for (int k = 0; k < 4; k++) acc[i][j][k] = 0.f;

    auto load_stage = [&](int cn) {
        uint32_t uS = uDyn + (uint32_t)((cn % 3) * SB);
        long kc = (long)cn * 32;
#pragma unroll
        for (int m0 = 0; m0 < MT; m0 += 64)
            cpa16(uS + (m0 + r) * SROW + s * 16, Ahp + kc + (long)(m0 + r) * ld + s * 8);
#pragma unroll
        for (int m0 = 0; m0 < MT; m0 += 64)
            cpa16(uS + (MT + m0 + r) * SROW + s * 16, Alp + kc + (long)(m0 + r) * ld + s * 8);
        cpa16(uS + (2 * MT + r) * SROW + s * 16, Whp + kc + (long)r * ld + s * 8);
        cpa16(uS + (2 * MT + BN + r) * SROW + s * 16, Wlp + kc + (long)r * ld + s * 8);
    };

    load_stage(0); cpa_commit();
    load_stage(1); cpa_commit();

    uint32_t aRowOff = (uint32_t)((wm * 64 + (lane & 15)) * SROW) + ((lane >> 4) ? 16u : 0u);
    uint32_t bRowOff = (uint32_t)((wn * 16 + (((lane >> 4) & 1) << 3) + (lane & 7)) * SROW)
                     + (((lane >> 3) & 1) ? 16u : 0u);

#pragma unroll 1
    for (int c = 0; c < kchunks; c++) {
        cpa_wait<1>();
        __syncthreads();
        int cn = c + 2;
        if (cn < kchunks) load_stage(cn);
        cpa_commit();

        uint32_t uS  = uDyn + (uint32_t)((c % 3) * SB);
        uint32_t uAh = uS;
        uint32_t uAl = uS + MT * SROW;
        uint32_t uWh = uS + 2 * MT * SROW;
        uint32_t uWl = uS + (2 * MT + BN) * SROW;
#pragma unroll
        for (int ks = 0; ks < 2; ks++) {
            uint32_t ah[4][4], al[4][4];
#pragma unroll
            for (int mf = 0; mf < 4; mf++) {
                ldsm4(ah[mf][0], ah[mf][1], ah[mf][2], ah[mf][3],
                      uAh + aRowOff + (uint32_t)(mf * 16 * SROW) + (uint32_t)(ks * 32));
                ldsm4(al[mf][0], al[mf][1], al[mf][2], al[mf][3],
                      uAl + aRowOff + (uint32_t)(mf * 16 * SROW) + (uint32_t)(ks * 32));
            }
            uint32_t bh[2][2], bl[2][2];
            {
                uint32_t q0, q1, q2, q3;
                ldsm4(q0, q1, q2, q3, uWh + bRowOff + (uint32_t)(ks * 32));
                bh[0][0] = q0; bh[0][1] = q1; bh[1][0] = q2; bh[1][1] = q3;
                ldsm4(q0, q1, q2, q3, uWl + bRowOff + (uint32_t)(ks * 32));
                bl[0][0] = q0; bl[0][1] = q1; bl[1][0] = q2; bl[1][1] = q3;
            }
#pragma unroll
            for (int mf = 0; mf < 4; mf++)
#pragma unroll
                for (int nf = 0; nf < 2; nf++) {
                    mma16816(acc[mf][nf], ah[mf], bh[nf]);
                    mma16816(acc[mf][nf], ah[mf], bl[nf]);
                    mma16816(acc[mf][nf], al[mf], bh[nf]);
                }
        }
    }

#pragma unroll
    for (int mf = 0; mf < 4; mf++) {
        int rr = rowBase + wm * 64 + mf * 16 + (lane >> 2);
#pragma unroll
        for (int nf = 0; nf < 2; nf++) {
            int cc = colBase + wn * 16 + nf * 8 + (lane & 3) * 2;
            if (cc < N) {
                float* p0 = C0 + (long)rr * N + cc;
                p0[0] = acc[mf][nf][0];
                if (cc + 1 < N) p0[1] = acc[mf][nf][1];
                float* p1 = C0 + (long)(rr + 8) * N + cc;
                p1[0] = acc[mf][nf][2];
                if (cc + 1 < N) p1[1] = acc[mf][nf][3];
            }
        }
    }
}

// ---------------- GEMM B: M64xN64, 4-stage pair pipeline (out_proj/head) ----------------
__global__ __launch_bounds__(256) void mma_gemm_b(
    const __nv_bfloat16* __restrict__ Ah, const __nv_bfloat16* __restrict__ Al,
    const __nv_bfloat16* __restrict__ Wh, const __nv_bfloat16* __restrict__ Wl,
    const float* __restrict__ bias, float* __restrict__ C0, float* __restrict__ C1,
    int N, int ld, int kchunks, int kzOff)
{
    constexpr int MT = 64;
    constexpr int BN = 64;
    constexpr int SB = (2 * MT + 2 * BN) * SROW;   // 20480
    extern __shared__ __align__(16) char dsm[];

    int tid = threadIdx.x;
    int lane = tid & 31, wid = tid >> 5;
    int wm = wid >> 2, wn = wid & 3;
    int rowBase = blockIdx.y * MT;
    int colBase = blockIdx.x * BN;
    int z = blockIdx.z;
    float* C = z ? C1 : C0;
    uint32_t uDyn = smem_u32(dsm);

    const __nv_bfloat16* Ahp = Ah + (long)rowBase * ld + (long)z * kzOff;
    const __nv_bfloat16* Alp = Al + (long)rowBase * ld + (long)z * kzOff;
    const __nv_bfloat16* Whp = Wh + (long)colBase * ld + (long)z * kzOff;
    const __nv_bfloat16* Wlp = Wl + (long)colBase * ld + (long)z * kzOff;

    int r = tid >> 2, s = tid & 3;

    float acc[2][2][4];
#pragma unroll
    for (int i = 0; i < 2; i++)
#pragma unroll
        for (int j = 0; j < 2; j++)
#pragma unroll
            for (int k = 0; k < 4; k++) acc[i][j][k] = 0.f;

    auto load_stage = [&](int cn) {
        uint32_t uS = uDyn + (uint32_t)((cn & 3) * SB);
        long kc = (long)cn * 32;
        cpa16(uS + r * SROW + s * 16,                 Ahp + kc + (long)r * ld + s * 8);
        cpa16(uS + (MT + r) * SROW + s * 16,          Alp + kc + (long)r * ld + s * 8);
        cpa16(uS + (2 * MT + r) * SROW + s * 16,      Whp + kc + (long)r * ld + s * 8);
        cpa16(uS + (2 * MT + BN + r) * SROW + s * 16, Wlp + kc + (long)r * ld + s * 8);
    };

    load_stage(0); cpa_commit();
    load_stage(1); cpa_commit();

    uint32_t aRowOff = (uint32_t)((wm * 32 + (lane & 15)) * SROW) + ((lane >> 4) ? 16u : 0u);
    uint32_t bRowOff = (uint32_t)((wn * 16 + (((lane >> 4) & 1) << 3) + (lane & 7)) * SROW)
                     + (((lane >> 3) & 1) ? 16u : 0u);

    int pairs = kchunks >> 1;
#pragma unroll 1
    for (int p = 0; p < pairs; p++) {
        cpa_wait<0>();
        __syncthreads();
        int cn = 2 * p + 2;
        if (cn < kchunks) {
            load_stage(cn);     cpa_commit();
            load_stage(cn + 1); cpa_commit();
        }
#pragma unroll
        for (int sub = 0; sub < 4; sub++) {
            int cc = 2 * p + (sub >> 1);
            int ks = sub & 1;
            uint32_t uS  = uDyn + (uint32_t)((cc & 3) * SB);
            uint32_t off = (uint32_t)(ks * 32);
            uint32_t ah[2][4], al[2][4];
#pragma unroll
            for (int mf = 0; mf < 2; mf++) {
                ldsm4(ah[mf][0], ah[mf][1], ah[mf][2], ah[mf][3],
                      uS + aRowOff + (uint32_t)(mf * 16 * SROW) + off);
                ldsm4(al[mf][0], al[mf][1], al[mf][2], al[mf][3],
                      uS + MT * SROW + aRowOff + (uint32_t)(mf * 16 * SROW) + off);
            }
            uint32_t bh[2][2], bl[2][2];
            {
                uint32_t q0, q1, q2, q3;
                ldsm4(q0, q1, q2, q3, uS + 2 * MT * SROW + bRowOff + off);
                bh[0][0] = q0; bh[0][1] = q1; bh[1][0] = q2; bh[1][1] = q3;
                ldsm4(q0, q1, q2, q3, uS + (2 * MT + BN) * SROW + bRowOff + off);
                bl[0][0] = q0; bl[0][1] = q1; bl[1][0] = q2; bl[1][1] = q3;
            }
#pragma unroll
            for (int mf = 0; mf < 2; mf++)
#pragma unroll
                for (int nf = 0; nf < 2; nf++) {
                    mma16816(acc[mf][nf], ah[mf], bh[nf]);
                    mma16816(acc[mf][nf], ah[mf], bl[nf]);
                    mma16816(acc[mf][nf], al[mf], bh[nf]);
                }
        }
    }

#pragma unroll
    for (int mf = 0; mf < 2; mf++) {
        int rr = rowBase + wm * 32 + mf * 16 + (lane >> 2);
#pragma unroll
        for (int nf = 0; nf < 2; nf++) {
            int cc = colBase + wn * 16 + nf * 8 + (lane & 3) * 2;
            if (cc < N) {
                float b0 = bias ? bias[cc] : 0.f;
                float b1 = bias ? ((cc + 1 < N) ? bias[cc + 1] : 0.f) : 0.f;
                float* p0 = C + (long)rr * N + cc;
                p0[0] = acc[mf][nf][0] + b0;
                if (cc + 1 < N) p0[1] = acc[mf][nf][1] + b1;
                float* p1 = C + (long)(rr + 8) * N + cc;
                p1[0] = acc[mf][nf][2] + b0;
                if (cc + 1 < N) p1[1] = acc[mf][nf][3] + b1;
            }
        }
    }
}

// ---------------- FUSED mid-section (256 blocks, 4 barriers) ----------------
#define SH_BYTES 35840
#define CONVXQ (MROWS * D_INNER / 4)    // 262144 (x-columns only)
#define DTQ    (MROWS * NHEADS / 4)     // 4096
__global__ __launch_bounds__(256, 2) void fused_mid(
    const float* __restrict__ cw, const float* __restrict__ cb,
    const float* __restrict__ dtb, const float* __restrict__ A_log,
    const float* __restrict__ Dv, const float* __restrict__ rw,
    int barBase)
{
    __shared__ __align__(16) char sh[SH_BYTES];
    int bb = blockIdx.x;
    int tid = threadIdx.x;
    int lane = tid & 31;

    // ===== Phase A/B merged =====
    for (int q = bb * 256 + tid; q < CONVXQ + DTQ; q += 65536) {
        if (q < CONVXQ) {
            int m = q >> 8;
            int c = (q & 255) * 4;
            int b = m >> 9, l = m & 511;
            float4 a = *(const float4*)(cb + c);
            float4 w0 = *(const float4*)(cw + (c + 0) * 4);
            float4 w1 = *(const float4*)(cw + (c + 1) * 4);
            float4 w2 = *(const float4*)(cw + (c + 2) * 4);
            float4 w3 = *(const float4*)(cw + (c + 3) * 4);
            float wa0[4] = {w0.x, w0.y, w0.z, w0.w};
            float wa1[4] = {w1.x, w1.y, w1.z, w1.w};
            float wa2[4] = {w2.x, w2.y, w2.z, w2.w};
            float wa3[4] = {w3.x, w3.y, w3.z, w3.w};
#pragma unroll
            for (int k = 0; k < 4; k++) {
                int ls = l + k - 3;
                if (ls >= 0) {
                    float4 v = *(const float4*)(g_zx + (long)((b << 9) + ls) * D_IN_PROJ + D_INNER + c);
                    a.x = fmaf(v.x, wa0[k], a.x);
                    a.y = fmaf(v.y, wa1[k], a.y);
                    a.z = fmaf(v.z, wa2[k], a.z);
                    a.w = fmaf(v.w, wa3[k], a.w);
                }
            }
            a.x = a.x / (1.f + __expf(-a.x));
            a.y = a.y / (1.f + __expf(-a.y));
            a.z = a.z / (1.f + __expf(-a.z));
            a.w = a.w / (1.f + __expf(-a.w));
            *(float4*)(g_xbc + (long)m * CONV_DIM + c) = a;
        } else {
            int rq = q - CONVXQ;
            int m = rq >> 2, h = (rq & 3) * 4;
#pragma unroll
            for (int j = 0; j < 4; j++) {
                float v = g_zx[(long)m * D_IN_PROJ + D_INNER + CONV_DIM + h + j] + dtb[h + j];
                float dt = (v > 20.f) ? v : log1pf(expf(v));
                float A = -expf(A_log[h + j]);
                g_dt[m * NHEADS + h + j] = dt;
                g_ldA[m * NHEADS + h + j] = dt * A;
            }
        }
    }

    {
        float (*sB64)[65] = (float(*)[65])sh;
        float (*sC8)[65]  = (float(*)[65])(sh + 64 * 65 * 4);
        int cbIdx = bb & 15;
        int half  = (bb >> 4) & 1;
        int slice = bb >> 5;
        int b = cbIdx >> 3, c = cbIdx & 7;
        int mBase = b * SEQ + c * QCH;
        for (int i = tid; i < 64 * 64; i += 256) {
            int s2 = i >> 6, n = i & 63;
            int ch = D_INNER + half * 64 + n;
            int m = mBase + s2;
            float v = conv_silu_1(cw, cb, m, ch);
            sB64[s2][n] = v;
            g_xbc[(long)m * CONV_DIM + ch] = v;
        }
        for (int i = tid; i < 8 * 64; i += 256) {
            int t = i >> 6, n = i & 63;
            int ch = D_INNER + D_STATE + half * 64 + n;
            int m = mBase + slice * 8 + t;
            float v = conv_silu_1(cw, cb, m, ch);
            sC8[t][n] = v;
            g_xbc[(long)m * CONV_DIM + ch] = v;
        }
        __syncthreads();
        int t = tid >> 5;
        long base = (long)cbIdx * (QCH * QCH);
#pragma unroll
        for (int ss = 0; ss < 2; ss++) {
            int s2 = lane + ss * 32;
            float acc = 0.f;
#pragma unroll
            for (int n = 0; n < 64; n++) acc = fmaf(sC8[t][n], sB64[s2][n], acc);
            g_CB[half][base + (slice * 8 + t) * 64 + s2] = acc;
        }
    }
    grid_barrier(barBase + 0);

    // ===== Phase C: cumsum L, G, y_local, S =====
    {
        float (*sA)[68] = (float(*)[68])sh;
        float (*sG)[68] = (float(*)[68])(sh + 64 * 68 * 4);
        float* sL  = (float*)(sh + 2 * 64 * 68 * 4);
        float* sDt = sL + 64;
        int c = bb & 7, bh = bb >> 3;
        int b = bh >> 4, h = bh & 15;
        int mBase = b * SEQ + c * QCH;
        int ty = tid >> 4, tx = tid & 15;
        int t4 = tid >> 2, j16 = (tid & 3) * 16;
        {
            const float* src = g_xbc + (long)(mBase + t4) * CONV_DIM + h * HEADDIM + j16;
#pragma unroll
            for (int q = 0; q < 4; q++) {
                float4 v = *(const float4*)(src + q * 4);
                sA[t4][j16 + q * 4 + 0] = v.x; sA[t4][j16 + q * 4 + 1] = v.y;
                sA[t4][j16 + q * 4 + 2] = v.z; sA[t4][j16 + q * 4 + 3] = v.w;
            }
        }
        if (tid < 64) {
            sDt[tid] = g_dt[(mBase + tid) * NHEADS + h];
            sL[tid]  = g_ldA[(mBase + tid) * NHEADS + h];
        }
        __syncthreads();
        if (tid < 64) {
            float v = sL[tid];
#pragma unroll
            for (int o = 1; o < 32; o <<= 1) {
                float n = __shfl_up_sync(0xffffffffu, v, o);
                if (lane >= o) v += n;
            }
            sL[tid] = v;
        }
        __syncthreads();
        if (tid >= 32 && tid < 64) sL[tid] += sL[31];
        __syncthreads();
        if (tid < 64) {
            g_cumL[bb * QCH + tid] = sL[tid];
            if (tid == 63) g_eLtot[bb] = __expf(sL[63]);
        }
        long cbbase = (long)((b << 3) + c) * (QCH * QCH);
#pragma unroll
        for (int i = 0; i < 4; i++) {
            int t = ty * 4 + i;
#pragma unroll
            for (int j = 0; j < 4; j++) {
                int s2 = tx * 4 + j;
                float g = 0.f;
                if (s2 <= t) {
                    float raw = g_CB[0][cbbase + t * 64 + s2] + g_CB[1][cbbase + t * 64 + s2];
                    g = raw * __expf(sL[t] - sL[s2]) * sDt[s2];
                }
                sG[t][s2] = g;
            }
        }
        __syncthreads();
        {
            float yv[4][4];
#pragma unroll
            for (int i = 0; i < 4; i++)
#pragma unroll
                for (int j = 0; j < 4; j++) yv[i][j] = 0.f;
#pragma unroll 4
            for (int s2 = 0; s2 < 64; s2++) {
                float av[4];
#pragma unroll
                for (int i = 0; i < 4; i++) av[i] = sG[ty * 4 + i][s2];
                float4 b4 = *(const float4*)&sA[s2][tx * 4];
                float bv[4] = {b4.x, b4.y, b4.z, b4.w};
#pragma unroll
                for (int i = 0; i < 4; i++)
#pragma unroll
                    for (int j = 0; j < 4; j++) yv[i][j] = fmaf(av[i], bv[j], yv[i][j]);
            }
            float Dval = Dv[h];
#pragma unroll
            for (int i = 0; i < 4; i++) {
                int t = ty * 4 + i;
#pragma unroll
                for (int j = 0; j < 4; j++) {
                    int p = tx * 4 + j;
                    g_y[(long)(mBase + t) * D_INNER + h * HEADDIM + p] = yv[i][j] + Dval * sA[t][p];
                }
            }
        }
        __syncthreads();
        {
            float w = __expf(sL[63] - sL[t4]) * sDt[t4];
#pragma unroll
            for (int q = 0; q < 16; q++) sA[t4][j16 + q] *= w;
        }
        long sbase = (long)bb * (HEADDIM * D_STATE);
#pragma unroll 1
        for (int nh = 0; nh < 2; nh++) {
            __syncthreads();
            {
                const float* bsrc = g_xbc + (long)(mBase + t4) * CONV_DIM + D_INNER + nh * 64 + j16;
#pragma unroll
                for (int q = 0; q < 4; q++) {
                    float4 v = *(const float4*)(bsrc + q * 4);
                    sG[t4][j16 + q * 4 + 0] = v.x; sG[t4][j16 + q * 4 + 1] = v.y;
                    sG[t4][j16 + q * 4 + 2] = v.z; sG[t4][j16 + q * 4 + 3] = v.w;
                }
            }
            __syncthreads();
            float sv[4][4];
#pragma unroll
            for (int i = 0; i < 4; i++)
#pragma unroll
                for (int j = 0; j < 4; j++) sv[i][j] = 0.f;
#pragma unroll 4
            for (int t = 0; t < 64; t++) {
                float4 a4 = *(const float4*)&sA[t][ty * 4];
                float4 b4 = *(const float4*)&sG[t][tx * 4];
                float av[4] = {a4.x, a4.y, a4.z, a4.w};
                float bv[4] = {b4.x, b4.y, b4.z, b4.w};
#pragma unroll
                for (int i = 0; i < 4; i++)
#pragma unroll
                    for (int j = 0; j < 4; j++) sv[i][j] = fmaf(av[i], bv[j], sv[i][j]);
            }
#pragma unroll
            for (int i = 0; i < 4; i++) {
                int p = ty * 4 + i;
#pragma unroll
                for (int j = 0; j < 4; j++)
                    g_S[sbase + (long)p * D_STATE + nh * 64 + tx * 4 + j] = sv[i][j];
            }
        }
    }
    grid_barrier(barBase + 1);

    // ===== Phase D: inter-chunk recurrence, 256-wide =====
    {
        int bh = bb >> 3, slice = bb & 7;
        float H[4];
#pragma unroll
        for (int k = 0; k < 4; k++) H[k] = 0.f;
#pragma unroll 1
        for (int c = 0; c < NCHUNK; c++) {
            long base = ((long)(bh * NCHUNK + c)) * HEADDIM * D_STATE + slice * 1024;
            float el = g_eLtot[bh * NCHUNK + c];
#pragma unroll
            for (int k = 0; k < 4; k++) {
                long e = base + tid + k * 256;
                g_Hs[e] = H[k];
                H[k] = el * H[k] + g_S[e];
            }
        }
    }
    grid_barrier(barBase + 2);

    // ===== Phase E: y += exp(L_t) * C_t . H_start =====
    {
        float (*sTa)[72] = (float(*)[72])sh;
        float (*sTh)[72] = (float(*)[72])(sh + 16 * 72 * 4);
        float* sEL = (float*)(sh + 2 * 16 * 72 * 4);
        int c = bb & 7, bh = bb >> 3;
        int b = bh >> 4, h = bh & 15;
        int mBase = b * SEQ + c * QCH;
        int ty = tid >> 4, tx = tid & 15;
        if (tid < 64) sEL[tid] = __expf(g_cumL[bb * QCH + tid]);

        float acc[4][4];
#pragma unroll
        for (int i = 0; i < 4; i++)
#pragma unroll
            for (int j = 0; j < 4; j++) acc[i][j] = 0.f;

        long hbase = (long)bb * (HEADDIM * D_STATE);
#pragma unroll 1
        for (int n0 = 0; n0 < D_STATE; n0 += 16) {
            __syncthreads();
            {
                int t = tid >> 2, jj = (tid & 3) * 4;
                float4 cv = *(const float4*)(g_xbc + (long)(mBase + t) * CONV_DIM + D_INNER + D_STATE + n0 + jj);
                sTa[jj + 0][t] = cv.x; sTa[jj + 1][t] = cv.y; sTa[jj + 2][t] = cv.z; sTa[jj + 3][t] = cv.w;
                float4 hv = *(const float4*)(g_Hs + hbase + (long)t * D_STATE + n0 + jj);
                sTh[jj + 0][t] = hv.x; sTh[jj + 1][t] = hv.y; sTh[jj + 2][t] = hv.z; sTh[jj + 3][t] = hv.w;
            }
            __syncthreads();
#pragma unroll
            for (int nn = 0; nn < 16; nn++) {
                float4 a4 = *(const float4*)&sTa[nn][ty * 4];
                float4 b4 = *(const float4*)&sTh[nn][tx * 4];
                float av[4] = {a4.x, a4.y, a4.z, a4.w};
                float bv[4] = {b4.x, b4.y, b4.z, b4.w};
#pragma unroll
                for (int i = 0; i < 4; i++)
#pragma unroll
                    for (int j = 0; j < 4; j++) acc[i][j] = fmaf(av[i], bv[j], acc[i][j]);
            }
        }
#pragma unroll
        for (int i = 0; i < 4; i++) {
            int t = ty * 4 + i;
            float e = sEL[t];
#pragma unroll
            for (int j = 0; j < 4; j++) {
                int p = tx * 4 + j;
                long idx = (long)(mBase + t) * D_INNER + h * HEADDIM + p;
                g_y[idx] += e * acc[i][j];
            }
        }
    }
    grid_barrier(barBase + 3);

    // ===== Phase F: gate + RMSNorm + split =====
    {
        float* red = (float*)sh;
#pragma unroll 1
        for (int rr = 0; rr < 4; rr++) {
            int m = bb * 4 + rr;
            float vals[4];
            float ss = 0.f;
#pragma unroll
            for (int i = 0; i < 4; i++) {
                int c = tid + i * 256;
                float z = g_zx[(long)m * D_IN_PROJ + c];
                float gate = z / (1.f + __expf(-z));
                float v = g_y[(long)m * D_INNER + c] * gate;
                vals[i] = v;
                ss = fmaf(v, v, ss);
            }
#pragma unroll
            for (int o = 16; o; o >>= 1) ss += __shfl_xor_sync(0xffffffffu, ss, o);
            __syncthreads();
            if (lane == 0) red[tid >> 5] = ss;
            __syncthreads();
            float tot = 0.f;
#pragma unroll
            for (int i = 0; i < 8; i++) tot += red[i];
            float rs = rsqrtf(tot * (1.f / D_INNER) + 1e-5f);
#pragma unroll
            for (int i = 0; i < 4; i++) {
                int c = tid + i * 256;
                float v = vals[i] * rs * rw[c];
                split1(v, g_ah[(long)m * D_INNER + c], g_al[(long)m * D_INNER + c]);
            }
        }
    }
}

// ---------------- residual + LayerNorm + split (4 rows/block) ----------------
__global__ __launch_bounds__(256) void res_ln_split(const float* __restrict__ lw,
                                                    const float* __restrict__ lb) {
    int t = threadIdx.x;
    __shared__ float red[8];
#pragma unroll 1
    for (int rr = 0; rr < 4; rr++) {
        int m = blockIdx.x * 4 + rr;
        long base = (long)m * D_MODEL;
        float v0 = g_y2[base + t]       + g_y2b[base + t]       + g_x[base + t];
        float v1 = g_y2[base + t + 256] + g_y2b[base + t + 256] + g_x[base + t + 256];
        float s = v0 + v1;
#pragma unroll
        for (int o = 16; o; o >>= 1) s += __shfl_xor_sync(0xffffffffu, s, o);
        __syncthreads();
        if ((t & 31) == 0) red[t >> 5] = s;
        __syncthreads();
        float tot = 0.f;
#pragma unroll
        for (int i = 0; i < 8; i++) tot += red[i];
        float mu = tot * (1.f / D_MODEL);
        float c0 = v0 - mu, c1 = v1 - mu;
        float ss = c0 * c0 + c1 * c1;
#pragma unroll
        for (int o = 16; o; o >>= 1) ss += __shfl_xor_sync(0xffffffffu, ss, o);
        __syncthreads();
        if ((t & 31) == 0) red[t >> 5] = ss;
        __syncthreads();
        float vtot = 0.f;
#pragma unroll
        for (int i = 0; i < 8; i++) vtot += red[i];
        float rs = rsqrtf(vtot * (1.f / D_MODEL) + 1e-5f);
        float o0 = c0 * rs * lw[t]       + lb[t];
        float o1 = c1 * rs * lw[t + 256] + lb[t + 256];
        g_x[base + t]       = o0;
        g_x[base + t + 256] = o1;
        split1(o0, g_ah[base + t],       g_al[base + t]);
        split1(o1, g_ah[base + t + 256], g_al[base + t + 256]);
    }
}

// ---------------- launch ----------------
#define DSMA (3 * (256 + 128) * SROW)   // 92160
#define DSMB (4 * (128 + 128) * SROW)   // 81920
extern "C" void kernel_launch(void* const* d_in, const int* in_sizes, int n_in,
                              void* d_out, int out_size) {
    const int*   tokens    = (const int*)  d_in[0];
    const float* embedding = (const float*)d_in[1];
    const float* in_proj_w = (const float*)d_in[2];
    const float* conv_w    = (const float*)d_in[3];
    const float* conv_b    = (const float*)d_in[4];
    const float* dt_bias   = (const float*)d_in[5];
    const float* A_log     = (const float*)d_in[6];
    const float* Dv        = (const float*)d_in[7];
    const float* rms_w     = (const float*)d_in[8];
    const float* out_proj_w= (const float*)d_in[9];
    const float* ln_w      = (const float*)d_in[10];
    const float* ln_b      = (const float*)d_in[11];
    const float* head_w    = (const float*)d_in[12];
    const float* head_b    = (const float*)d_in[13];
    float* out = (float*)d_out;

    cudaFuncSetAttribute(mma_gemm_a, cudaFuncAttributeMaxDynamicSharedMemorySize, DSMA);
    cudaFuncSetAttribute(mma_gemm_b, cudaFuncAttributeMaxDynamicSharedMemorySize, DSMB);

    void *p_zx, *p_y2, *p_y2b, *p_ah, *p_al;
    void *p_whin, *p_wlin, *p_whout, *p_wlout, *p_whhd, *p_wlhd;
    cudaGetSymbolAddress(&p_zx, g_zx);
    cudaGetSymbolAddress(&p_y2, g_y2);
    cudaGetSymbolAddress(&p_y2b, g_y2b);
    cudaGetSymbolAddress(&p_ah, g_ah);
    cudaGetSymbolAddress(&p_al, g_al);
    cudaGetSymbolAddress(&p_whin,  g_wh_in);
    cudaGetSymbolAddress(&p_wlin,  g_wl_in);
    cudaGetSymbolAddress(&p_whout, g_wh_out);
    cudaGetSymbolAddress(&p_wlout, g_wl_out);
    cudaGetSymbolAddress(&p_whhd,  g_wh_hd);
    cudaGetSymbolAddress(&p_wlhd,  g_wl_hd);
    float* dzx  = (float*)p_zx;
    float* dy2  = (float*)p_y2;
    float* dy2b = (float*)p_y2b;
    __nv_bfloat16* ah = (__nv_bfloat16*)p_ah;
    __nv_bfloat16* al = (__nv_bfloat16*)p_al;
    __nv_bfloat16* whin  = (__nv_bfloat16*)p_whin;
    __nv_bfloat16* wlin  = (__nv_bfloat16*)p_wlin;
    __nv_bfloat16* whout = (__nv_bfloat16*)p_whout;
    __nv_bfloat16* wlout = (__nv_bfloat16*)p_wlout;
    __nv_bfloat16* whhd  = (__nv_bfloat16*)p_whhd;
    __nv_bfloat16* wlhd  = (__nv_bfloat16*)p_wlhd;

    prep_kernel<<<(int)((PREP_TOTAL / 4 + 255) / 256), 256>>>(
        in_proj_w, out_proj_w, head_w, tokens, embedding);

    for (int i = 0; i < NB; i++) {
        // in_proj: M128xN64, 3-stage -> 304 CTAs (best measured config)
        mma_gemm_a<<<dim3(NPAD_IN / 64, MROWS / 128, 1), 256, DSMA>>>(
            ah, al, whin + (long)i * NPAD_IN * D_MODEL, wlin + (long)i * NPAD_IN * D_MODEL,
            dzx, D_IN_PROJ, D_MODEL, D_MODEL / 32);
        fused_mid<<<256, 256>>>(
            conv_w + (long)i * CONV_DIM * D_CONV, conv_b + (long)i * CONV_DIM,
            dt_bias + i * NHEADS, A_log + i * NHEADS,
            Dv + i * NHEADS, rms_w + (long)i * D_INNER, i * 4);
        mma_gemm_b<<<dim3(D_MODEL / 64, MROWS / 64, 2), 256, DSMB>>>(
            ah, al, whout + (long)i * D_MODEL * D_INNER, wlout + (long)i * D_MODEL * D_INNER,
            nullptr, dy2, dy2b, D_MODEL, D_INNER, 512 / 32, 512);
        res_ln_split<<<MROWS / 4, 256>>>(ln_w + i * D_MODEL, ln_b + i * D_MODEL);
    }

    mma_gemm_b<<<dim3(NPAD_HD / 64, MROWS / 64, 1), 256, DSMB>>>(
        ah, al, whhd, wlhd, head_b, out, nullptr, LABELS, D_MODEL, D_MODEL / 32, 0);
}

// round 16
// speedup vs baseline: 1.0132x; 1.0094x over previous
#include <cuda_runtime.h>
#include <cuda_bf16.h>
#include <math.h>
#include <stdint.h>

// ---------------- problem constants ----------------
#define NB        2
#define D_MODEL   512
#define D_STATE   128
#define D_CONV    4
#define HEADDIM   64
#define D_INNER   1024
#define NHEADS    16
#define CONV_DIM  1280
#define D_IN_PROJ 2320
#define NPAD_IN   2432
#define LABELS    1000
#define NPAD_HD   1024
#define BATCH     2
#define SEQ       512
#define MROWS     (BATCH*SEQ)
#define QCH       64
#define NCHUNK    (SEQ/QCH)     // 8
#define BH        (BATCH*NHEADS)// 32
#define BC        (BATCH*NCHUNK)// 16

// ---------------- scratch ----------------
__device__ float g_x  [MROWS * D_MODEL];
__device__ float g_zx [MROWS * D_IN_PROJ];
__device__ float g_xbc[MROWS * CONV_DIM];
__device__ float g_dt [MROWS * NHEADS];
__device__ float g_ldA[MROWS * NHEADS];
__device__ float g_y  [MROWS * D_INNER];
__device__ float g_y2 [MROWS * D_MODEL];
__device__ float g_y2b[MROWS * D_MODEL];
__device__ float g_S   [BH * NCHUNK * HEADDIM * D_STATE];
__device__ float g_Hs  [BH * NCHUNK * HEADDIM * D_STATE];
__device__ float g_cumL[BH * NCHUNK * QCH];
__device__ float g_eLtot[BH * NCHUNK];
__device__ float g_CB  [2][BC * QCH * QCH];
__device__ int   g_gbar[16];
__device__ __nv_bfloat16 g_wh_in [NB][NPAD_IN * D_MODEL];
__device__ __nv_bfloat16 g_wl_in [NB][NPAD_IN * D_MODEL];
__device__ __nv_bfloat16 g_wh_out[NB][D_MODEL * D_INNER];
__device__ __nv_bfloat16 g_wl_out[NB][D_MODEL * D_INNER];
__device__ __nv_bfloat16 g_wh_hd [NPAD_HD * D_MODEL];
__device__ __nv_bfloat16 g_wl_hd [NPAD_HD * D_MODEL];
__device__ __nv_bfloat16 g_ah[MROWS * D_INNER];
__device__ __nv_bfloat16 g_al[MROWS * D_INNER];

// ---------------- PTX helpers (portable sm_80+ only) ----------------
__device__ __forceinline__ uint32_t smem_u32(const void* p) {
    uint32_t a;
    asm("{ .reg .u64 t; cvta.to.shared.u64 t, %1; cvt.u32.u64 %0, t; }" : "=r"(a) : "l"(p));
    return a;
}
__device__ __forceinline__ void cpa16(uint32_t dst, const void* src) {
    asm volatile("cp.async.cg.shared.global [%0],[%1],16;" :: "r"(dst), "l"(src) : "memory");
}
__device__ __forceinline__ void cpa_commit() {
    asm volatile("cp.async.commit_group;" ::: "memory");
}
template<int N> __device__ __forceinline__ void cpa_wait() {
    asm volatile("cp.async.wait_group %0;" :: "n"(N) : "memory");
}
__device__ __forceinline__ void ldsm4(uint32_t& r0, uint32_t& r1, uint32_t& r2, uint32_t& r3, uint32_t addr) {
    asm volatile("ldmatrix.sync.aligned.m8n8.x4.shared.b16 {%0,%1,%2,%3},[%4];"
                 : "=r"(r0), "=r"(r1), "=r"(r2), "=r"(r3) : "r"(addr));
}
__device__ __forceinline__ void mma16816(float* d, const uint32_t* a, const uint32_t* b) {
    asm volatile(
        "mma.sync.aligned.m16n8k16.row.col.f32.bf16.bf16.f32 "
        "{%0,%1,%2,%3},{%4,%5,%6,%7},{%8,%9},{%0,%1,%2,%3};"
        : "+f"(d[0]), "+f"(d[1]), "+f"(d[2]), "+f"(d[3])
        : "r"(a[0]), "r"(a[1]), "r"(a[2]), "r"(a[3]), "r"(b[0]), "r"(b[1]));
}
__device__ __forceinline__ void split1(float v, __nv_bfloat16& h, __nv_bfloat16& l) {
    __nv_bfloat16 hv = __float2bfloat16(v);
    h = hv;
    l = __float2bfloat16(v - __bfloat162float(hv));
}
__device__ __forceinline__ void grid_barrier(int idx) {
    __syncthreads();
    if (threadIdx.x == 0) {
        __threadfence();
        atomicAdd(&g_gbar[idx], 1);
        while (*((volatile int*)&g_gbar[idx]) < 256) __nanosleep(64);
        __threadfence();
    }
    __syncthreads();
}
// conv4 + silu for one (row m, channel c) of xBC
__device__ __forceinline__ float conv_silu_1(const float* __restrict__ cw,
                                             const float* __restrict__ cb,
                                             int m, int c) {
    int b = m >> 9, l = m & 511;
    float acc = cb[c];
#pragma unroll
    for (int k = 0; k < D_CONV; k++) {
        int ls = l + k - 3;
        if (ls >= 0)
            acc = fmaf(g_zx[(long)((b << 9) + ls) * D_IN_PROJ + D_INNER + c], cw[c * 4 + k], acc);
    }
    return acc / (1.f + __expf(-acc));
}

// ---------------- merged weight splits + embedding, 4 elems/thread ----------------
#define SEG_IN  ((long)NPAD_IN * D_MODEL)
#define SEG_OUT ((long)D_MODEL * D_INNER)
#define WSPLIT_TOTAL (2*SEG_IN + 2*SEG_OUT + SEG_OUT)
#define PREP_TOTAL (WSPLIT_TOTAL + (long)MROWS * D_MODEL)
__global__ void prep_kernel(const float* __restrict__ inw,
                            const float* __restrict__ outw,
                            const float* __restrict__ hw,
                            const int* __restrict__ tokens,
                            const float* __restrict__ emb) {
    long idx = ((long)blockIdx.x * 256 + threadIdx.x) * 4;
    if (blockIdx.x == 0 && threadIdx.x < 16) g_gbar[threadIdx.x] = 0;
    if (idx >= PREP_TOTAL) return;
    if (idx >= WSPLIT_TOTAL) {
        long e = idx - WSPLIT_TOTAL;
        int m = (int)(e >> 9), d = (int)(e & 511);
        float4 v = *(const float4*)(emb + (long)tokens[m] * D_MODEL + d);
        *(float4*)(g_x + e) = v;
        split1(v.x, g_ah[e + 0], g_al[e + 0]);
        split1(v.y, g_ah[e + 1], g_al[e + 1]);
        split1(v.z, g_ah[e + 2], g_al[e + 2]);
        split1(v.w, g_ah[e + 3], g_al[e + 3]);
        return;
    }
    const float* src; __nv_bfloat16 *dh, *dl; int rows, ksh; long off;
    if (idx < 2 * SEG_IN) {
        int layer = idx >= SEG_IN;
        off = idx - (long)layer * SEG_IN;
        src = inw + (long)layer * D_IN_PROJ * D_MODEL;
        dh = g_wh_in[layer]; dl = g_wl_in[layer]; rows = D_IN_PROJ; ksh = 9;
    } else if (idx < 2 * SEG_IN + 2 * SEG_OUT) {
        long r = idx - 2 * SEG_IN;
        int layer = r >= SEG_OUT;
        off = r - (long)layer * SEG_OUT;
        src = outw + (long)layer * SEG_OUT;
        dh = g_wh_out[layer]; dl = g_wl_out[layer]; rows = D_MODEL; ksh = 10;
    } else {
        off = idx - 2 * SEG_IN - 2 * SEG_OUT;
        src = hw; dh = g_wh_hd; dl = g_wl_hd; rows = LABELS; ksh = 9;
    }
    int r = (int)(off >> ksh), c = (int)(off & ((1 << ksh) - 1));
    float4 v = make_float4(0.f, 0.f, 0.f, 0.f);
    if (r < rows) v = *(const float4*)(src + ((long)r << ksh) + c);
    split1(v.x, dh[off + 0], dl[off + 0]);
    split1(v.y, dh[off + 1], dl[off + 1]);
    split1(v.z, dh[off + 2], dl[off + 2]);
    split1(v.w, dh[off + 3], dl[off + 3]);
}

// ---------------- GEMM A: M128xN64 tile, 3-stage (for in_proj) ----------------
#define SROW 80
__global__ __launch_bounds__(256) void mma_gemm_a(
    const __nv_bfloat16* __restrict__ Ah, const __nv_bfloat16* __restrict__ Al,
    const __nv_bfloat16* __restrict__ Wh, const __nv_bfloat16* __restrict__ Wl,
    float* __restrict__ C0, int N, int ld, int kchunks)
{
    constexpr int MT = 128;
    constexpr int BN = 64;
    constexpr int SB = (2 * MT + 2 * BN) * SROW;
    extern __shared__ __align__(16) char dsm[];

    int tid = threadIdx.x;
    int lane = tid & 31, wid = tid >> 5;
    int wm = wid >> 2, wn = wid & 3;
    int rowBase = blockIdx.y * MT;
    int colBase = blockIdx.x * BN;
    uint32_t uDyn = smem_u32(dsm);

    const __nv_bfloat16* Ahp = Ah + (long)rowBase * ld;
    const __nv_bfloat16* Alp = Al + (long)rowBase * ld;
    const __nv_bfloat16* Whp = Wh + (long)colBase * ld;
    const __nv_bfloat16* Wlp = Wl + (long)colBase * ld;

    int r = tid >> 2, s = tid & 3;

    float acc[4][2][4];
#pragma unroll
    for (int i = 0; i < 4; i++)
#pragma unroll
        for (int j = 0; j < 2; j++)
#pragma unroll
            for (int k = 0; k < 4; k++) acc[i][j][k] = 0.f;

    auto load_stage = [&](int cn) {
        uint32_t uS = uDyn + (uint32_t)((cn % 3) * SB);
        long kc = (long)cn * 32;
#pragma unroll
        for (int m0 = 0; m0 < MT; m0 += 64)
            cpa16(uS + (m0 + r) * SROW + s * 16, Ahp + kc + (long)(m0 + r) * ld + s * 8);
#pragma unroll
        for (int m0 = 0; m0 < MT; m0 += 64)
            cpa16(uS + (MT + m0 + r) * SROW + s * 16, Alp + kc + (long)(m0 + r) * ld + s * 8);
        cpa16(uS + (2 * MT + r) * SROW + s * 16, Whp + kc + (long)r * ld + s * 8);
        cpa16(uS + (2 * MT + BN + r) * SROW + s * 16, Wlp + kc + (long)r * ld + s * 8);
    };

    load_stage(0); cpa_commit();
    load_stage(1); cpa_commit();

    uint32_t aRowOff = (uint32_t)((wm * 64 + (lane & 15)) * SROW) + ((lane >> 4) ? 16u : 0u);
    uint32_t bRowOff = (uint32_t)((wn * 16 + (((lane >> 4) & 1) << 3) + (lane & 7)) * SROW)
                     + (((lane >> 3) & 1) ? 16u : 0u);

#pragma unroll 1
    for (int c = 0; c < kchunks; c++) {
        cpa_wait<1>();
        __syncthreads();
        int cn = c + 2;
        if (cn < kchunks) load_stage(cn);
        cpa_commit();

        uint32_t uS  = uDyn + (uint32_t)((c % 3) * SB);
        uint32_t uAh = uS;
        uint32_t uAl = uS + MT * SROW;
        uint32_t uWh = uS + 2 * MT * SROW;
        uint32_t uWl = uS + (2 * MT + BN) * SROW;
#pragma unroll
        for (int ks = 0; ks < 2; ks++) {
            uint32_t ah[4][4], al[4][4];
#pragma unroll
            for (int mf = 0; mf < 4; mf++) {
                ldsm4(ah[mf][0], ah[mf][1], ah[mf][2], ah[mf][3],
                      uAh + aRowOff + (uint32_t)(mf * 16 * SROW) + (uint32_t)(ks * 32));
                ldsm4(al[mf][0], al[mf][1], al[mf][2], al[mf][3],
                      uAl + aRowOff + (uint32_t)(mf * 16 * SROW) + (uint32_t)(ks * 32));
            }
            uint32_t bh[2][2], bl[2][2];
            {
                uint32_t q0, q1, q2, q3;
                ldsm4(q0, q1, q2, q3, uWh + bRowOff + (uint32_t)(ks * 32));
                bh[0][0] = q0; bh[0][1] = q1; bh[1][0] = q2; bh[1][1] = q3;
                ldsm4(q0, q1, q2, q3, uWl + bRowOff + (uint32_t)(ks * 32));
                bl[0][0] = q0; bl[0][1] = q1; bl[1][0] = q2; bl[1][1] = q3;
            }
#pragma unroll
            for (int mf = 0; mf < 4; mf++)
#pragma unroll
                for (int nf = 0; nf < 2; nf++) {
                    mma16816(acc[mf][nf], ah[mf], bh[nf]);
                    mma16816(acc[mf][nf], ah[mf], bl[nf]);
                    mma16816(acc[mf][nf], al[mf], bh[nf]);
                }
        }
    }

#pragma unroll
    for (int mf = 0; mf < 4; mf++) {
        int rr = rowBase + wm * 64 + mf * 16 + (lane >> 2);
#pragma unroll
        for (int nf = 0; nf < 2; nf++) {
            int cc = colBase + wn * 16 + nf * 8 + (lane & 3) * 2;
            if (cc < N) {
                float* p0 = C0 + (long)rr * N + cc;
                p0[0] = acc[mf][nf][0];
                if (cc + 1 < N) p0[1] = acc[mf][nf][1];
                float* p1 = C0 + (long)(rr + 8) * N + cc;
                p1[0] = acc[mf][nf][2];
                if (cc + 1 < N) p1[1] = acc[mf][nf][3];
            }
        }
    }
}

// ---------------- GEMM B: M64xN64, 4-stage pair pipeline (out_proj/head) ----------------
__global__ __launch_bounds__(256) void mma_gemm_b(
    const __nv_bfloat16* __restrict__ Ah, const __nv_bfloat16* __restrict__ Al,
    const __nv_bfloat16* __restrict__ Wh, const __nv_bfloat16* __restrict__ Wl,
    const float* __restrict__ bias, float* __restrict__ C0, float* __restrict__ C1,
    int N, int ld, int kchunks, int kzOff)
{
    constexpr int MT = 64;
    constexpr int BN = 64;
    constexpr int SB = (2 * MT + 2 * BN) * SROW;   // 20480
    extern __shared__ __align__(16) char dsm[];

    int tid = threadIdx.x;
    int lane = tid & 31, wid = tid >> 5;
    int wm = wid >> 2, wn = wid & 3;
    int rowBase = blockIdx.y * MT;
    int colBase = blockIdx.x * BN;
    int z = blockIdx.z;
    float* C = z ? C1 : C0;
    uint32_t uDyn = smem_u32(dsm);

    const __nv_bfloat16* Ahp = Ah + (long)rowBase * ld + (long)z * kzOff;
    const __nv_bfloat16* Alp = Al + (long)rowBase * ld + (long)z * kzOff;
    const __nv_bfloat16* Whp = Wh + (long)colBase * ld + (long)z * kzOff;
    const __nv_bfloat16* Wlp = Wl + (long)colBase * ld + (long)z * kzOff;

    int r = tid >> 2, s = tid & 3;

    float acc[2][2][4];
#pragma unroll
    for (int i = 0; i < 2; i++)
#pragma unroll
        for (int j = 0; j < 2; j++)
#pragma unroll
            for (int k = 0; k < 4; k++) acc[i][j][k] = 0.f;

    auto load_stage = [&](int cn) {
        uint32_t uS = uDyn + (uint32_t)((cn & 3) * SB);
        long kc = (long)cn * 32;
        cpa16(uS + r * SROW + s * 16,                 Ahp + kc + (long)r * ld + s * 8);
        cpa16(uS + (MT + r) * SROW + s * 16,          Alp + kc + (long)r * ld + s * 8);
        cpa16(uS + (2 * MT + r) * SROW + s * 16,      Whp + kc + (long)r * ld + s * 8);
        cpa16(uS + (2 * MT + BN + r) * SROW + s * 16, Wlp + kc + (long)r * ld + s * 8);
    };

    load_stage(0); cpa_commit();
    load_stage(1); cpa_commit();

    uint32_t aRowOff = (uint32_t)((wm * 32 + (lane & 15)) * SROW) + ((lane >> 4) ? 16u : 0u);
    uint32_t bRowOff = (uint32_t)((wn * 16 + (((lane >> 4) & 1) << 3) + (lane & 7)) * SROW)
                     + (((lane >> 3) & 1) ? 16u : 0u);

    int pairs = kchunks >> 1;
#pragma unroll 1
    for (int p = 0; p < pairs; p++) {
        cpa_wait<0>();
        __syncthreads();
        int cn = 2 * p + 2;
        if (cn < kchunks) {
            load_stage(cn);     cpa_commit();
            load_stage(cn + 1); cpa_commit();
        }
#pragma unroll
        for (int sub = 0; sub < 4; sub++) {
            int cc = 2 * p + (sub >> 1);
            int ks = sub & 1;
            uint32_t uS  = uDyn + (uint32_t)((cc & 3) * SB);
            uint32_t off = (uint32_t)(ks * 32);
            uint32_t ah[2][4], al[2][4];
#pragma unroll
            for (int mf = 0; mf < 2; mf++) {
                ldsm4(ah[mf][0], ah[mf][1], ah[mf][2], ah[mf][3],
                      uS + aRowOff + (uint32_t)(mf * 16 * SROW) + off);
                ldsm4(al[mf][0], al[mf][1], al[mf][2], al[mf][3],
                      uS + MT * SROW + aRowOff + (uint32_t)(mf * 16 * SROW) + off);
            }
            uint32_t bh[2][2], bl[2][2];
            {
                uint32_t q0, q1, q2, q3;
                ldsm4(q0, q1, q2, q3, uS + 2 * MT * SROW + bRowOff + off);
                bh[0][0] = q0; bh[0][1] = q1; bh[1][0] = q2; bh[1][1] = q3;
                ldsm4(q0, q1, q2, q3, uS + (2 * MT + BN) * SROW + bRowOff + off);
                bl[0][0] = q0; bl[0][1] = q1; bl[1][0] = q2; bl[1][1] = q3;
            }
#pragma unroll
            for (int mf = 0; mf < 2; mf++)
#pragma unroll
                for (int nf = 0; nf < 2; nf++) {
                    mma16816(acc[mf][nf], ah[mf], bh[nf]);
                    mma16816(acc[mf][nf], ah[mf], bl[nf]);
                    mma16816(acc[mf][nf], al[mf], bh[nf]);
                }
        }
    }

#pragma unroll
    for (int mf = 0; mf < 2; mf++) {
        int rr = rowBase + wm * 32 + mf * 16 + (lane >> 2);
#pragma unroll
        for (int nf = 0; nf < 2; nf++) {
            int cc = colBase + wn * 16 + nf * 8 + (lane & 3) * 2;
            if (cc < N) {
                float b0 = bias ? bias[cc] : 0.f;
                float b1 = bias ? ((cc + 1 < N) ? bias[cc + 1] : 0.f) : 0.f;
                float* p0 = C + (long)rr * N + cc;
                p0[0] = acc[mf][nf][0] + b0;
                if (cc + 1 < N) p0[1] = acc[mf][nf][1] + b1;
                float* p1 = C + (long)(rr + 8) * N + cc;
                p1[0] = acc[mf][nf][2] + b0;
                if (cc + 1 < N) p1[1] = acc[mf][nf][3] + b1;
            }
        }
    }
}

// ---------------- FUSED mid-section (256 blocks, 4 barriers) ----------------
#define SH_BYTES 35840
#define CONVXQ (MROWS * D_INNER / 4)    // 262144 (x-columns only)
#define DTQ    (MROWS * NHEADS / 4)     // 4096
__global__ __launch_bounds__(256, 2) void fused_mid(
    const float* __restrict__ cw, const float* __restrict__ cb,
    const float* __restrict__ dtb, const float* __restrict__ A_log,
    const float* __restrict__ Dv, const float* __restrict__ rw,
    int barBase)
{
    __shared__ __align__(16) char sh[SH_BYTES];
    int bb = blockIdx.x;
    int tid = threadIdx.x;
    int lane = tid & 31;

    // ===== Phase A/B merged =====
    for (int q = bb * 256 + tid; q < CONVXQ + DTQ; q += 65536) {
        if (q < CONVXQ) {
            int m = q >> 8;
            int c = (q & 255) * 4;
            int b = m >> 9, l = m & 511;
            float4 a = *(const float4*)(cb + c);
            float4 w0 = *(const float4*)(cw + (c + 0) * 4);
            float4 w1 = *(const float4*)(cw + (c + 1) * 4);
            float4 w2 = *(const float4*)(cw + (c + 2) * 4);
            float4 w3 = *(const float4*)(cw + (c + 3) * 4);
            float wa0[4] = {w0.x, w0.y, w0.z, w0.w};
            float wa1[4] = {w1.x, w1.y, w1.z, w1.w};
            float wa2[4] = {w2.x, w2.y, w2.z, w2.w};
            float wa3[4] = {w3.x, w3.y, w3.z, w3.w};
#pragma unroll
            for (int k = 0; k < 4; k++) {
                int ls = l + k - 3;
                if (ls >= 0) {
                    float4 v = *(const float4*)(g_zx + (long)((b << 9) + ls) * D_IN_PROJ + D_INNER + c);
                    a.x = fmaf(v.x, wa0[k], a.x);
                    a.y = fmaf(v.y, wa1[k], a.y);
                    a.z = fmaf(v.z, wa2[k], a.z);
                    a.w = fmaf(v.w, wa3[k], a.w);
                }
            }
            a.x = a.x / (1.f + __expf(-a.x));
            a.y = a.y / (1.f + __expf(-a.y));
            a.z = a.z / (1.f + __expf(-a.z));
            a.w = a.w / (1.f + __expf(-a.w));
            *(float4*)(g_xbc + (long)m * CONV_DIM + c) = a;
        } else {
            int rq = q - CONVXQ;
            int m = rq >> 2, h = (rq & 3) * 4;
#pragma unroll
            for (int j = 0; j < 4; j++) {
                float v = g_zx[(long)m * D_IN_PROJ + D_INNER + CONV_DIM + h + j] + dtb[h + j];
                float dt = (v > 20.f) ? v : log1pf(expf(v));
                float A = -expf(A_log[h + j]);
                g_dt[m * NHEADS + h + j] = dt;
                g_ldA[m * NHEADS + h + j] = dt * A;
            }
        }
    }

    {
        float (*sB64)[65] = (float(*)[65])sh;
        float (*sC8)[65]  = (float(*)[65])(sh + 64 * 65 * 4);
        int cbIdx = bb & 15;
        int half  = (bb >> 4) & 1;
        int slice = bb >> 5;
        int b = cbIdx >> 3, c = cbIdx & 7;
        int mBase = b * SEQ + c * QCH;
        for (int i = tid; i < 64 * 64; i += 256) {
            int s2 = i >> 6, n = i & 63;
            int ch = D_INNER + half * 64 + n;
            int m = mBase + s2;
            float v = conv_silu_1(cw, cb, m, ch);
            sB64[s2][n] = v;
            g_xbc[(long)m * CONV_DIM + ch] = v;
        }
        for (int i = tid; i < 8 * 64; i += 256) {
            int t = i >> 6, n = i & 63;
            int ch = D_INNER + D_STATE + half * 64 + n;
            int m = mBase + slice * 8 + t;
            float v = conv_silu_1(cw, cb, m, ch);
            sC8[t][n] = v;
            g_xbc[(long)m * CONV_DIM + ch] = v;
        }
        __syncthreads();
        int t = tid >> 5;
        long base = (long)cbIdx * (QCH * QCH);
#pragma unroll
        for (int ss = 0; ss < 2; ss++) {
            int s2 = lane + ss * 32;
            float acc = 0.f;
#pragma unroll
            for (int n = 0; n < 64; n++) acc = fmaf(sC8[t][n], sB64[s2][n], acc);
            g_CB[half][base + (slice * 8 + t) * 64 + s2] = acc;
        }
    }
    grid_barrier(barBase + 0);

    // ===== Phase C: cumsum L, G, y_local, S =====
    {
        float (*sA)[68] = (float(*)[68])sh;
        float (*sG)[68] = (float(*)[68])(sh + 64 * 68 * 4);
        float* sL  = (float*)(sh + 2 * 64 * 68 * 4);
        float* sDt = sL + 64;
        int c = bb & 7, bh = bb >> 3;
        int b = bh >> 4, h = bh & 15;
        int mBase = b * SEQ + c * QCH;
        int ty = tid >> 4, tx = tid & 15;
        int t4 = tid >> 2, j16 = (tid & 3) * 16;
        {
            const float* src = g_xbc + (long)(mBase + t4) * CONV_DIM + h * HEADDIM + j16;
#pragma unroll
            for (int q = 0; q < 4; q++) {
                float4 v = *(const float4*)(src + q * 4);
                sA[t4][j16 + q * 4 + 0] = v.x; sA[t4][j16 + q * 4 + 1] = v.y;
                sA[t4][j16 + q * 4 + 2] = v.z; sA[t4][j16 + q * 4 + 3] = v.w;
            }
        }
        if (tid < 64) {
            sDt[tid] = g_dt[(mBase + tid) * NHEADS + h];
            sL[tid]  = g_ldA[(mBase + tid) * NHEADS + h];
        }
        __syncthreads();
        if (tid < 64) {
            float v = sL[tid];
#pragma unroll
            for (int o = 1; o < 32; o <<= 1) {
                float n = __shfl_up_sync(0xffffffffu, v, o);
                if (lane >= o) v += n;
            }
            sL[tid] = v;
        }
        __syncthreads();
        if (tid >= 32 && tid < 64) sL[tid] += sL[31];
        __syncthreads();
        if (tid < 64) {
            g_cumL[bb * QCH + tid] = sL[tid];
            if (tid == 63) g_eLtot[bb] = __expf(sL[63]);
        }
        long cbbase = (long)((b << 3) + c) * (QCH * QCH);
#pragma unroll
        for (int i = 0; i < 4; i++) {
            int t = ty * 4 + i;
#pragma unroll
            for (int j = 0; j < 4; j++) {
                int s2 = tx * 4 + j;
                float g = 0.f;
                if (s2 <= t) {
                    float raw = g_CB[0][cbbase + t * 64 + s2] + g_CB[1][cbbase + t * 64 + s2];
                    g = raw * __expf(sL[t] - sL[s2]) * sDt[s2];
                }
                sG[t][s2] = g;
            }
        }
        __syncthreads();
        {
            float yv[4][4];
#pragma unroll
            for (int i = 0; i < 4; i++)
#pragma unroll
                for (int j = 0; j < 4; j++) yv[i][j] = 0.f;
#pragma unroll 4
            for (int s2 = 0; s2 < 64; s2++) {
                float av[4];
#pragma unroll
                for (int i = 0; i < 4; i++) av[i] = sG[ty * 4 + i][s2];
                float4 b4 = *(const float4*)&sA[s2][tx * 4];
                float bv[4] = {b4.x, b4.y, b4.z, b4.w};
#pragma unroll
                for (int i = 0; i < 4; i++)
#pragma unroll
                    for (int j = 0; j < 4; j++) yv[i][j] = fmaf(av[i], bv[j], yv[i][j]);
            }
            float Dval = Dv[h];
#pragma unroll
            for (int i = 0; i < 4; i++) {
                int t = ty * 4 + i;
#pragma unroll
                for (int j = 0; j < 4; j++) {
                    int p = tx * 4 + j;
                    g_y[(long)(mBase + t) * D_INNER + h * HEADDIM + p] = yv[i][j] + Dval * sA[t][p];
                }
            }
        }
        __syncthreads();
        {
            float w = __expf(sL[63] - sL[t4]) * sDt[t4];
#pragma unroll
            for (int q = 0; q < 16; q++) sA[t4][j16 + q] *= w;
        }
        long sbase = (long)bb * (HEADDIM * D_STATE);
#pragma unroll 1
        for (int nh = 0; nh < 2; nh++) {
            __syncthreads();
            {
                const float* bsrc = g_xbc + (long)(mBase + t4) * CONV_DIM + D_INNER + nh * 64 + j16;
#pragma unroll
                for (int q = 0; q < 4; q++) {
                    float4 v = *(const float4*)(bsrc + q * 4);
                    sG[t4][j16 + q * 4 + 0] = v.x; sG[t4][j16 + q * 4 + 1] = v.y;
                    sG[t4][j16 + q * 4 + 2] = v.z; sG[t4][j16 + q * 4 + 3] = v.w;
                }
            }
            __syncthreads();
            float sv[4][4];
#pragma unroll
            for (int i = 0; i < 4; i++)
#pragma unroll
                for (int j = 0; j < 4; j++) sv[i][j] = 0.f;
#pragma unroll 4
            for (int t = 0; t < 64; t++) {
                float4 a4 = *(const float4*)&sA[t][ty * 4];
                float4 b4 = *(const float4*)&sG[t][tx * 4];
                float av[4] = {a4.x, a4.y, a4.z, a4.w};
                float bv[4] = {b4.x, b4.y, b4.z, b4.w};
#pragma unroll
                for (int i = 0; i < 4; i++)
#pragma unroll
                    for (int j = 0; j < 4; j++) sv[i][j] = fmaf(av[i], bv[j], sv[i][j]);
            }
#pragma unroll
            for (int i = 0; i < 4; i++) {
                int p = ty * 4 + i;
#pragma unroll
                for (int j = 0; j < 4; j++)
                    g_S[sbase + (long)p * D_STATE + nh * 64 + tx * 4 + j] = sv[i][j];
            }
        }
    }
    grid_barrier(barBase + 1);

    // ===== Phase D: inter-chunk recurrence, 256-wide =====
    {
        int bh = bb >> 3, slice = bb & 7;
        float H[4];
#pragma unroll
        for (int k = 0; k < 4; k++) H[k] = 0.f;
#pragma unroll 1
        for (int c = 0; c < NCHUNK; c++) {
            long base = ((long)(bh * NCHUNK + c)) * HEADDIM * D_STATE + slice * 1024;
            float el = g_eLtot[bh * NCHUNK + c];
#pragma unroll
            for (int k = 0; k < 4; k++) {
                long e = base + tid + k * 256;
                g_Hs[e] = H[k];
                H[k] = el * H[k] + g_S[e];
            }
        }
    }
    grid_barrier(barBase + 2);

    // ===== Phase E: y += exp(L_t) * C_t . H_start =====
    {
        float (*sTa)[72] = (float(*)[72])sh;
        float (*sTh)[72] = (float(*)[72])(sh + 16 * 72 * 4);
        float* sEL = (float*)(sh + 2 * 16 * 72 * 4);
        int c = bb & 7, bh = bb >> 3;
        int b = bh >> 4, h = bh & 15;
        int mBase = b * SEQ + c * QCH;
        int ty = tid >> 4, tx = tid & 15;
        if (tid < 64) sEL[tid] = __expf(g_cumL[bb * QCH + tid]);

        float acc[4][4];
#pragma unroll
        for (int i = 0; i < 4; i++)
#pragma unroll
            for (int j = 0; j < 4; j++) acc[i][j] = 0.f;

        long hbase = (long)bb * (HEADDIM * D_STATE);
#pragma unroll 1
        for (int n0 = 0; n0 < D_STATE; n0 += 16) {
            __syncthreads();
            {
                int t = tid >> 2, jj = (tid & 3) * 4;
                float4 cv = *(const float4*)(g_xbc + (long)(mBase + t) * CONV_DIM + D_INNER + D_STATE + n0 + jj);
                sTa[jj + 0][t] = cv.x; sTa[jj + 1][t] = cv.y; sTa[jj + 2][t] = cv.z; sTa[jj + 3][t] = cv.w;
                float4 hv = *(const float4*)(g_Hs + hbase + (long)t * D_STATE + n0 + jj);
                sTh[jj + 0][t] = hv.x; sTh[jj + 1][t] = hv.y; sTh[jj + 2][t] = hv.z; sTh[jj + 3][t] = hv.w;
            }
            __syncthreads();
#pragma unroll
            for (int nn = 0; nn < 16; nn++) {
                float4 a4 = *(const float4*)&sTa[nn][ty * 4];
                float4 b4 = *(const float4*)&sTh[nn][tx * 4];
                float av[4] = {a4.x, a4.y, a4.z, a4.w};
                float bv[4] = {b4.x, b4.y, b4.z, b4.w};
#pragma unroll
                for (int i = 0; i < 4; i++)
#pragma unroll
                    for (int j = 0; j < 4; j++) acc[i][j] = fmaf(av[i], bv[j], acc[i][j]);
            }
        }
#pragma unroll
        for (int i = 0; i < 4; i++) {
            int t = ty * 4 + i;
            float e = sEL[t];
#pragma unroll
            for (int j = 0; j < 4; j++) {
                int p = tx * 4 + j;
                long idx = (long)(mBase + t) * D_INNER + h * HEADDIM + p;
                g_y[idx] += e * acc[i][j];
            }
        }
    }
    grid_barrier(barBase + 3);

    // ===== Phase F: gate + RMSNorm + split =====
    {
        float* red = (float*)sh;
#pragma unroll 1
        for (int rr = 0; rr < 4; rr++) {
            int m = bb * 4 + rr;
            float vals[4];
            float ss = 0.f;
#pragma unroll
            for (int i = 0; i < 4; i++) {
                int c = tid + i * 256;
                float z = g_zx[(long)m * D_IN_PROJ + c];
                float gate = z / (1.f + __expf(-z));
                float v = g_y[(long)m * D_INNER + c] * gate;
                vals[i] = v;
                ss = fmaf(v, v, ss);
            }
#pragma unroll
            for (int o = 16; o; o >>= 1) ss += __shfl_xor_sync(0xffffffffu, ss, o);
            __syncthreads();
            if (lane == 0) red[tid >> 5] = ss;
            __syncthreads();
            float tot = 0.f;
#pragma unroll
            for (int i = 0; i < 8; i++) tot += red[i];
            float rs = rsqrtf(tot * (1.f / D_INNER) + 1e-5f);
#pragma unroll
            for (int i = 0; i < 4; i++) {
                int c = tid + i * 256;
                float v = vals[i] * rs * rw[c];
                split1(v, g_ah[(long)m * D_INNER + c], g_al[(long)m * D_INNER + c]);
            }
        }
    }
}

// ---------------- residual + LayerNorm + split ----------------
__global__ __launch_bounds__(256) void res_ln_split(const float* __restrict__ lw,
                                                    const float* __restrict__ lb) {
    int m = blockIdx.x;
    int t = threadIdx.x;
    __shared__ float red[8];
    long base = (long)m * D_MODEL;
    float v0 = g_y2[base + t]       + g_y2b[base + t]       + g_x[base + t];
    float v1 = g_y2[base + t + 256] + g_y2b[base + t + 256] + g_x[base + t + 256];
    float s = v0 + v1;
#pragma unroll
    for (int o = 16; o; o >>= 1) s += __shfl_xor_sync(0xffffffffu, s, o);
    if ((t & 31) == 0) red[t >> 5] = s;
    __syncthreads();
    float tot = 0.f;
#pragma unroll
    for (int i = 0; i < 8; i++) tot += red[i];
    float mu = tot * (1.f / D_MODEL);
    __syncthreads();
    float c0 = v0 - mu, c1 = v1 - mu;
    float ss = c0 * c0 + c1 * c1;
#pragma unroll
    for (int o = 16; o; o >>= 1) ss += __shfl_xor_sync(0xffffffffu, ss, o);
    if ((t & 31) == 0) red[t >> 5] = ss;
    __syncthreads();
    float vtot = 0.f;
#pragma unroll
    for (int i = 0; i < 8; i++) vtot += red[i];
    float rs = rsqrtf(vtot * (1.f / D_MODEL) + 1e-5f);
    float o0 = c0 * rs * lw[t]       + lb[t];
    float o1 = c1 * rs * lw[t + 256] + lb[t + 256];
    g_x[base + t]       = o0;
    g_x[base + t + 256] = o1;
    split1(o0, g_ah[base + t],       g_al[base + t]);
    split1(o1, g_ah[base + t + 256], g_al[base + t + 256]);
}

// ---------------- launch ----------------
#define DSMA (3 * (256 + 128) * SROW)   // 92160
#define DSMB (4 * (128 + 128) * SROW)   // 81920
extern "C" void kernel_launch(void* const* d_in, const int* in_sizes, int n_in,
                              void* d_out, int out_size) {
    const int*   tokens    = (const int*)  d_in[0];
    const float* embedding = (const float*)d_in[1];
    const float* in_proj_w = (const float*)d_in[2];
    const float* conv_w    = (const float*)d_in[3];
    const float* conv_b    = (const float*)d_in[4];
    const float* dt_bias   = (const float*)d_in[5];
    const float* A_log     = (const float*)d_in[6];
    const float* Dv        = (const float*)d_in[7];
    const float* rms_w     = (const float*)d_in[8];
    const float* out_proj_w= (const float*)d_in[9];
    const float* ln_w      = (const float*)d_in[10];
    const float* ln_b      = (const float*)d_in[11];
    const float* head_w    = (const float*)d_in[12];
    const float* head_b    = (const float*)d_in[13];
    float* out = (float*)d_out;

    cudaFuncSetAttribute(mma_gemm_a, cudaFuncAttributeMaxDynamicSharedMemorySize, DSMA);
    cudaFuncSetAttribute(mma_gemm_b, cudaFuncAttributeMaxDynamicSharedMemorySize, DSMB);

    void *p_zx, *p_y2, *p_y2b, *p_ah, *p_al;
    void *p_whin, *p_wlin, *p_whout, *p_wlout, *p_whhd, *p_wlhd;
    cudaGetSymbolAddress(&p_zx, g_zx);
    cudaGetSymbolAddress(&p_y2, g_y2);
    cudaGetSymbolAddress(&p_y2b, g_y2b);
    cudaGetSymbolAddress(&p_ah, g_ah);
    cudaGetSymbolAddress(&p_al, g_al);
    cudaGetSymbolAddress(&p_whin,  g_wh_in);
    cudaGetSymbolAddress(&p_wlin,  g_wl_in);
    cudaGetSymbolAddress(&p_whout, g_wh_out);
    cudaGetSymbolAddress(&p_wlout, g_wl_out);
    cudaGetSymbolAddress(&p_whhd,  g_wh_hd);
    cudaGetSymbolAddress(&p_wlhd,  g_wl_hd);
    float* dzx  = (float*)p_zx;
    float* dy2  = (float*)p_y2;
    float* dy2b = (float*)p_y2b;
    __nv_bfloat16* ah = (__nv_bfloat16*)p_ah;
    __nv_bfloat16* al = (__nv_bfloat16*)p_al;
    __nv_bfloat16* whin  = (__nv_bfloat16*)p_whin;
    __nv_bfloat16* wlin  = (__nv_bfloat16*)p_wlin;
    __nv_bfloat16* whout = (__nv_bfloat16*)p_whout;
    __nv_bfloat16* wlout = (__nv_bfloat16*)p_wlout;
    __nv_bfloat16* whhd  = (__nv_bfloat16*)p_whhd;
    __nv_bfloat16* wlhd  = (__nv_bfloat16*)p_wlhd;

    prep_kernel<<<(int)((PREP_TOTAL / 4 + 255) / 256), 256>>>(
        in_proj_w, out_proj_w, head_w, tokens, embedding);

    for (int i = 0; i < NB; i++) {
        // in_proj: M128xN64, 3-stage -> 304 CTAs
        mma_gemm_a<<<dim3(NPAD_IN / 64, MROWS / 128, 1), 256, DSMA>>>(
            ah, al, whin + (long)i * NPAD_IN * D_MODEL, wlin + (long)i * NPAD_IN * D_MODEL,
            dzx, D_IN_PROJ, D_MODEL, D_MODEL / 32);
        fused_mid<<<256, 256>>>(
            conv_w + (long)i * CONV_DIM * D_CONV, conv_b + (long)i * CONV_DIM,
            dt_bias + i * NHEADS, A_log + i * NHEADS,
            Dv + i * NHEADS, rms_w + (long)i * D_INNER, i * 4);
        mma_gemm_b<<<dim3(D_MODEL / 64, MROWS / 64, 2), 256, DSMB>>>(
            ah, al, whout + (long)i * D_MODEL * D_INNER, wlout + (long)i * D_MODEL * D_INNER,
            nullptr, dy2, dy2b, D_MODEL, D_INNER, 512 / 32, 512);
        res_ln_split<<<MROWS, 256>>>(ln_w + i * D_MODEL, ln_b + i * D_MODEL);
    }

    mma_gemm_b<<<dim3(NPAD_HD / 64, MROWS / 64, 1), 256, DSMB>>>(
        ah, al, whhd, wlhd, head_b, out, nullptr, LABELS, D_MODEL, D_MODEL / 32, 0);
}

// round 17
// speedup vs baseline: 1.0155x; 1.0023x over previous
#include <cuda_runtime.h>
#include <cuda_bf16.h>
#include <math.h>
#include <stdint.h>

// ---------------- problem constants ----------------
#define NB        2
#define D_MODEL   512
#define D_STATE   128
#define D_CONV    4
#define HEADDIM   64
#define D_INNER   1024
#define NHEADS    16
#define CONV_DIM  1280
#define D_IN_PROJ 2320
#define NPAD_IN   2432
#define LABELS    1000
#define NPAD_HD   1024
#define BATCH     2
#define SEQ       512
#define MROWS     (BATCH*SEQ)
#define QCH       64
#define NCHUNK    (SEQ/QCH)     // 8
#define BH        (BATCH*NHEADS)// 32
#define BC        (BATCH*NCHUNK)// 16

// ---------------- scratch ----------------
__device__ float g_x  [MROWS * D_MODEL];
__device__ float g_zx [MROWS * D_IN_PROJ];
__device__ float g_xbc[MROWS * CONV_DIM];
__device__ float g_dt [MROWS * NHEADS];
__device__ float g_ldA[MROWS * NHEADS];
__device__ float g_y  [MROWS * D_INNER];
__device__ float g_y2 [MROWS * D_MODEL];
__device__ float g_y2b[MROWS * D_MODEL];
__device__ float g_S   [BH * NCHUNK * HEADDIM * D_STATE];
__device__ float g_Hs  [BH * NCHUNK * HEADDIM * D_STATE];
__device__ float g_cumL[BH * NCHUNK * QCH];
__device__ float g_eLtot[BH * NCHUNK];
__device__ float g_CB  [2][BC * QCH * QCH];
__device__ int   g_gbar[16];
__device__ __nv_bfloat16 g_wh_in [NB][NPAD_IN * D_MODEL];
__device__ __nv_bfloat16 g_wl_in [NB][NPAD_IN * D_MODEL];
__device__ __nv_bfloat16 g_wh_out[NB][D_MODEL * D_INNER];
__device__ __nv_bfloat16 g_wl_out[NB][D_MODEL * D_INNER];
__device__ __nv_bfloat16 g_wh_hd [NPAD_HD * D_MODEL];
__device__ __nv_bfloat16 g_wl_hd [NPAD_HD * D_MODEL];
__device__ __nv_bfloat16 g_ah[MROWS * D_INNER];
__device__ __nv_bfloat16 g_al[MROWS * D_INNER];

// ---------------- PTX helpers (portable sm_80+ only) ----------------
__device__ __forceinline__ uint32_t smem_u32(const void* p) {
    uint32_t a;
    asm("{ .reg .u64 t; cvta.to.shared.u64 t, %1; cvt.u32.u64 %0, t; }" : "=r"(a) : "l"(p));
    return a;
}
__device__ __forceinline__ void cpa16(uint32_t dst, const void* src) {
    asm volatile("cp.async.cg.shared.global [%0],[%1],16;" :: "r"(dst), "l"(src) : "memory");
}
__device__ __forceinline__ void cpa_commit() {
    asm volatile("cp.async.commit_group;" ::: "memory");
}
template<int N> __device__ __forceinline__ void cpa_wait() {
    asm volatile("cp.async.wait_group %0;" :: "n"(N) : "memory");
}
__device__ __forceinline__ void ldsm4(uint32_t& r0, uint32_t& r1, uint32_t& r2, uint32_t& r3, uint32_t addr) {
    asm volatile("ldmatrix.sync.aligned.m8n8.x4.shared.b16 {%0,%1,%2,%3},[%4];"
                 : "=r"(r0), "=r"(r1), "=r"(r2), "=r"(r3) : "r"(addr));
}
__device__ __forceinline__ void mma16816(float* d, const uint32_t* a, const uint32_t* b) {
    asm volatile(
        "mma.sync.aligned.m16n8k16.row.col.f32.bf16.bf16.f32 "
        "{%0,%1,%2,%3},{%4,%5,%6,%7},{%8,%9},{%0,%1,%2,%3};"
        : "+f"(d[0]), "+f"(d[1]), "+f"(d[2]), "+f"(d[3])
        : "r"(a[0]), "r"(a[1]), "r"(a[2]), "r"(a[3]), "r"(b[0]), "r"(b[1]));
}
__device__ __forceinline__ void split1(float v, __nv_bfloat16& h, __nv_bfloat16& l) {
    __nv_bfloat16 hv = __float2bfloat16(v);
    h = hv;
    l = __float2bfloat16(v - __bfloat162float(hv));
}
__device__ __forceinline__ void grid_barrier(int idx) {
    __syncthreads();
    if (threadIdx.x == 0) {
        __threadfence();
        atomicAdd(&g_gbar[idx], 1);
        while (*((volatile int*)&g_gbar[idx]) < 256) __nanosleep(64);
        __threadfence();
    }
    __syncthreads();
}
// conv4 + silu for one (row m, channel c) of xBC
__device__ __forceinline__ float conv_silu_1(const float* __restrict__ cw,
                                             const float* __restrict__ cb,
                                             int m, int c) {
    int b = m >> 9, l = m & 511;
    float acc = cb[c];
#pragma unroll
    for (int k = 0; k < D_CONV; k++) {
        int ls = l + k - 3;
        if (ls >= 0)
            acc = fmaf(g_zx[(long)((b << 9) + ls) * D_IN_PROJ + D_INNER + c], cw[c * 4 + k], acc);
    }
    return acc / (1.f + __expf(-acc));
}

// ---------------- merged weight splits + embedding, 4 elems/thread ----------------
#define SEG_IN  ((long)NPAD_IN * D_MODEL)
#define SEG_OUT ((long)D_MODEL * D_INNER)
#define WSPLIT_TOTAL (2*SEG_IN + 2*SEG_OUT + SEG_OUT)
#define PREP_TOTAL (WSPLIT_TOTAL + (long)MROWS * D_MODEL)
__global__ void prep_kernel(const float* __restrict__ inw,
                            const float* __restrict__ outw,
                            const float* __restrict__ hw,
                            const int* __restrict__ tokens,
                            const float* __restrict__ emb) {
    long idx = ((long)blockIdx.x * 256 + threadIdx.x) * 4;
    if (blockIdx.x == 0 && threadIdx.x < 16) g_gbar[threadIdx.x] = 0;
    if (idx >= PREP_TOTAL) return;
    if (idx >= WSPLIT_TOTAL) {
        long e = idx - WSPLIT_TOTAL;
        int m = (int)(e >> 9), d = (int)(e & 511);
        float4 v = *(const float4*)(emb + (long)tokens[m] * D_MODEL + d);
        *(float4*)(g_x + e) = v;
        split1(v.x, g_ah[e + 0], g_al[e + 0]);
        split1(v.y, g_ah[e + 1], g_al[e + 1]);
        split1(v.z, g_ah[e + 2], g_al[e + 2]);
        split1(v.w, g_ah[e + 3], g_al[e + 3]);
        return;
    }
    const float* src; __nv_bfloat16 *dh, *dl; int rows, ksh; long off;
    if (idx < 2 * SEG_IN) {
        int layer = idx >= SEG_IN;
        off = idx - (long)layer * SEG_IN;
        src = inw + (long)layer * D_IN_PROJ * D_MODEL;
        dh = g_wh_in[layer]; dl = g_wl_in[layer]; rows = D_IN_PROJ; ksh = 9;
    } else if (idx < 2 * SEG_IN + 2 * SEG_OUT) {
        long r = idx - 2 * SEG_IN;
        int layer = r >= SEG_OUT;
        off = r - (long)layer * SEG_OUT;
        src = outw + (long)layer * SEG_OUT;
        dh = g_wh_out[layer]; dl = g_wl_out[layer]; rows = D_MODEL; ksh = 10;
    } else {
        off = idx - 2 * SEG_IN - 2 * SEG_OUT;
        src = hw; dh = g_wh_hd; dl = g_wl_hd; rows = LABELS; ksh = 9;
    }
    int r = (int)(off >> ksh), c = (int)(off & ((1 << ksh) - 1));
    float4 v = make_float4(0.f, 0.f, 0.f, 0.f);
    if (r < rows) v = *(const float4*)(src + ((long)r << ksh) + c);
    split1(v.x, dh[off + 0], dl[off + 0]);
    split1(v.y, dh[off + 1], dl[off + 1]);
    split1(v.z, dh[off + 2], dl[off + 2]);
    split1(v.w, dh[off + 3], dl[off + 3]);
}

// ---------------- GEMM A: M128xN64 tile, 3-stage (for in_proj) ----------------
#define SROW 80
__global__ __launch_bounds__(256) void mma_gemm_a(
    const __nv_bfloat16* __restrict__ Ah, const __nv_bfloat16* __restrict__ Al,
    const __nv_bfloat16* __restrict__ Wh, const __nv_bfloat16* __restrict__ Wl,
    float* __restrict__ C0, int N, int ld, int kchunks)
{
    constexpr int MT = 128;
    constexpr int BN = 64;
    constexpr int SB = (2 * MT + 2 * BN) * SROW;
    extern __shared__ __align__(16) char dsm[];

    int tid = threadIdx.x;
    int lane = tid & 31, wid = tid >> 5;
    int wm = wid >> 2, wn = wid & 3;
    int rowBase = blockIdx.y * MT;
    int colBase = blockIdx.x * BN;
    uint32_t uDyn = smem_u32(dsm);

    const __nv_bfloat16* Ahp = Ah + (long)rowBase * ld;
    const __nv_bfloat16* Alp = Al + (long)rowBase * ld;
    const __nv_bfloat16* Whp = Wh + (long)colBase * ld;
    const __nv_bfloat16* Wlp = Wl + (long)colBase * ld;

    int r = tid >> 2, s = tid & 3;

    float acc[4][2][4];
#pragma unroll
    for (int i = 0; i < 4; i++)
#pragma unroll
        for (int j = 0; j < 2; j++)
#pragma unroll
            for (int k = 0; k < 4; k++) acc[i][j][k] = 0.f;

    auto load_stage = [&](int cn) {
        uint32_t uS = uDyn + (uint32_t)((cn % 3) * SB);
        long kc = (long)cn * 32;
#pragma unroll
        for (int m0 = 0; m0 < MT; m0 += 64)
            cpa16(uS + (m0 + r) * SROW + s * 16, Ahp + kc + (long)(m0 + r) * ld + s * 8);
#pragma unroll
        for (int m0 = 0; m0 < MT; m0 += 64)
            cpa16(uS + (MT + m0 + r) * SROW + s * 16, Alp + kc + (long)(m0 + r) * ld + s * 8);
        cpa16(uS + (2 * MT + r) * SROW + s * 16, Whp + kc + (long)r * ld + s * 8);
        cpa16(uS + (2 * MT + BN + r) * SROW + s * 16, Wlp + kc + (long)r * ld + s * 8);
    };

    load_stage(0); cpa_commit();
    load_stage(1); cpa_commit();

    uint32_t aRowOff = (uint32_t)((wm * 64 + (lane & 15)) * SROW) + ((lane >> 4) ? 16u : 0u);
    uint32_t bRowOff = (uint32_t)((wn * 16 + (((lane >> 4) & 1) << 3) + (lane & 7)) * SROW)
                     + (((lane >> 3) & 1) ? 16u : 0u);

#pragma unroll 1
    for (int c = 0; c < kchunks; c++) {
        cpa_wait<1>();
        __syncthreads();
        int cn = c + 2;
        if (cn < kchunks) load_stage(cn);
        cpa_commit();

        uint32_t uS  = uDyn + (uint32_t)((c % 3) * SB);
        uint32_t uAh = uS;
        uint32_t uAl = uS + MT * SROW;
        uint32_t uWh = uS + 2 * MT * SROW;
        uint32_t uWl = uS + (2 * MT + BN) * SROW;
#pragma unroll
        for (int ks = 0; ks < 2; ks++) {
            uint32_t ah[4][4], al[4][4];
#pragma unroll
            for (int mf = 0; mf < 4; mf++) {
                ldsm4(ah[mf][0], ah[mf][1], ah[mf][2], ah[mf][3],
                      uAh + aRowOff + (uint32_t)(mf * 16 * SROW) + (uint32_t)(ks * 32));
                ldsm4(al[mf][0], al[mf][1], al[mf][2], al[mf][3],
                      uAl + aRowOff + (uint32_t)(mf * 16 * SROW) + (uint32_t)(ks * 32));
            }
            uint32_t bh[2][2], bl[2][2];
            {
                uint32_t q0, q1, q2, q3;
                ldsm4(q0, q1, q2, q3, uWh + bRowOff + (uint32_t)(ks * 32));
                bh[0][0] = q0; bh[0][1] = q1; bh[1][0] = q2; bh[1][1] = q3;
                ldsm4(q0, q1, q2, q3, uWl + bRowOff + (uint32_t)(ks * 32));
                bl[0][0] = q0; bl[0][1] = q1; bl[1][0] = q2; bl[1][1] = q3;
            }
#pragma unroll
            for (int mf = 0; mf < 4; mf++)
#pragma unroll
                for (int nf = 0; nf < 2; nf++) {
                    mma16816(acc[mf][nf], ah[mf], bh[nf]);
                    mma16816(acc[mf][nf], ah[mf], bl[nf]);
                    mma16816(acc[mf][nf], al[mf], bh[nf]);
                }
        }
    }

#pragma unroll
    for (int mf = 0; mf < 4; mf++) {
        int rr = rowBase + wm * 64 + mf * 16 + (lane >> 2);
#pragma unroll
        for (int nf = 0; nf < 2; nf++) {
            int cc = colBase + wn * 16 + nf * 8 + (lane & 3) * 2;
            if (cc < N) {
                float* p0 = C0 + (long)rr * N + cc;
                p0[0] = acc[mf][nf][0];
                if (cc + 1 < N) p0[1] = acc[mf][nf][1];
                float* p1 = C0 + (long)(rr + 8) * N + cc;
                p1[0] = acc[mf][nf][2];
                if (cc + 1 < N) p1[1] = acc[mf][nf][3];
            }
        }
    }
}

// ---------------- GEMM B: M64xN64, 4-stage pair pipeline (out_proj/head) ----------------
__global__ __launch_bounds__(256) void mma_gemm_b(
    const __nv_bfloat16* __restrict__ Ah, const __nv_bfloat16* __restrict__ Al,
    const __nv_bfloat16* __restrict__ Wh, const __nv_bfloat16* __restrict__ Wl,
    const float* __restrict__ bias, float* __restrict__ C0, float* __restrict__ C1,
    int N, int ld, int kchunks, int kzOff)
{
    constexpr int MT = 64;
    constexpr int BN = 64;
    constexpr int SB = (2 * MT + 2 * BN) * SROW;   // 20480
    extern __shared__ __align__(16) char dsm[];

    int tid = threadIdx.x;
    int lane = tid & 31, wid = tid >> 5;
    int wm = wid >> 2, wn = wid & 3;
    int rowBase = blockIdx.y * MT;
    int colBase = blockIdx.x * BN;
    int z = blockIdx.z;
    float* C = z ? C1 : C0;
    uint32_t uDyn = smem_u32(dsm);

    const __nv_bfloat16* Ahp = Ah + (long)rowBase * ld + (long)z * kzOff;
    const __nv_bfloat16* Alp = Al + (long)rowBase * ld + (long)z * kzOff;
    const __nv_bfloat16* Whp = Wh + (long)colBase * ld + (long)z * kzOff;
    const __nv_bfloat16* Wlp = Wl + (long)colBase * ld + (long)z * kzOff;

    int r = tid >> 2, s = tid & 3;

    float acc[2][2][4];
#pragma unroll
    for (int i = 0; i < 2; i++)
#pragma unroll
        for (int j = 0; j < 2; j++)
#pragma unroll
            for (int k = 0; k < 4; k++) acc[i][j][k] = 0.f;

    auto load_stage = [&](int cn) {
        uint32_t uS = uDyn + (uint32_t)((cn & 3) * SB);
        long kc = (long)cn * 32;
        cpa16(uS + r * SROW + s * 16,                 Ahp + kc + (long)r * ld + s * 8);
        cpa16(uS + (MT + r) * SROW + s * 16,          Alp + kc + (long)r * ld + s * 8);
        cpa16(uS + (2 * MT + r) * SROW + s * 16,      Whp + kc + (long)r * ld + s * 8);
        cpa16(uS + (2 * MT + BN + r) * SROW + s * 16, Wlp + kc + (long)r * ld + s * 8);
    };

    load_stage(0); cpa_commit();
    load_stage(1); cpa_commit();

    uint32_t aRowOff = (uint32_t)((wm * 32 + (lane & 15)) * SROW) + ((lane >> 4) ? 16u : 0u);
    uint32_t bRowOff = (uint32_t)((wn * 16 + (((lane >> 4) & 1) << 3) + (lane & 7)) * SROW)
                     + (((lane >> 3) & 1) ? 16u : 0u);

    int pairs = kchunks >> 1;
#pragma unroll 1
    for (int p = 0; p < pairs; p++) {
        cpa_wait<0>();
        __syncthreads();
        int cn = 2 * p + 2;
        if (cn < kchunks) {
            load_stage(cn);     cpa_commit();
            load_stage(cn + 1); cpa_commit();
        }
#pragma unroll
        for (int sub = 0; sub < 4; sub++) {
            int cc = 2 * p + (sub >> 1);
            int ks = sub & 1;
            uint32_t uS  = uDyn + (uint32_t)((cc & 3) * SB);
            uint32_t off = (uint32_t)(ks * 32);
            uint32_t ah[2][4], al[2][4];
#pragma unroll
            for (int mf = 0; mf < 2; mf++) {
                ldsm4(ah[mf][0], ah[mf][1], ah[mf][2], ah[mf][3],
                      uS + aRowOff + (uint32_t)(mf * 16 * SROW) + off);
                ldsm4(al[mf][0], al[mf][1], al[mf][2], al[mf][3],
                      uS + MT * SROW + aRowOff + (uint32_t)(mf * 16 * SROW) + off);
            }
            uint32_t bh[2][2], bl[2][2];
            {
                uint32_t q0, q1, q2, q3;
                ldsm4(q0, q1, q2, q3, uS + 2 * MT * SROW + bRowOff + off);
                bh[0][0] = q0; bh[0][1] = q1; bh[1][0] = q2; bh[1][1] = q3;
                ldsm4(q0, q1, q2, q3, uS + (2 * MT + BN) * SROW + bRowOff + off);
                bl[0][0] = q0; bl[0][1] = q1; bl[1][0] = q2; bl[1][1] = q3;
            }
#pragma unroll
            for (int mf = 0; mf < 2; mf++)
#pragma unroll
                for (int nf = 0; nf < 2; nf++) {
                    mma16816(acc[mf][nf], ah[mf], bh[nf]);
                    mma16816(acc[mf][nf], ah[mf], bl[nf]);
                    mma16816(acc[mf][nf], al[mf], bh[nf]);
                }
        }
    }

#pragma unroll
    for (int mf = 0; mf < 2; mf++) {
        int rr = rowBase + wm * 32 + mf * 16 + (lane >> 2);
#pragma unroll
        for (int nf = 0; nf < 2; nf++) {
            int cc = colBase + wn * 16 + nf * 8 + (lane & 3) * 2;
            if (cc < N) {
                float b0 = bias ? bias[cc] : 0.f;
                float b1 = bias ? ((cc + 1 < N) ? bias[cc + 1] : 0.f) : 0.f;
                float* p0 = C + (long)rr * N + cc;
                p0[0] = acc[mf][nf][0] + b0;
                if (cc + 1 < N) p0[1] = acc[mf][nf][1] + b1;
                float* p1 = C + (long)(rr + 8) * N + cc;
                p1[0] = acc[mf][nf][2] + b0;
                if (cc + 1 < N) p1[1] = acc[mf][nf][3] + b1;
            }
        }
    }
}

// ---------------- FUSED mid-section (256 blocks, 4 barriers) ----------------
#define SH_BYTES 35840
#define CONVXQ (MROWS * D_INNER / 4)    // 262144 (x-columns only)
#define DTQ    (MROWS * NHEADS / 4)     // 4096
__global__ __launch_bounds__(256, 2) void fused_mid(
    const float* __restrict__ cw, const float* __restrict__ cb,
    const float* __restrict__ dtb, const float* __restrict__ A_log,
    const float* __restrict__ Dv, const float* __restrict__ rw,
    int barBase)
{
    __shared__ __align__(16) char sh[SH_BYTES];
    int bb = blockIdx.x;
    int tid = threadIdx.x;
    int lane = tid & 31;

    // ===== Phase A/B merged =====
    for (int q = bb * 256 + tid; q < CONVXQ + DTQ; q += 65536) {
        if (q < CONVXQ) {
            int m = q >> 8;
            int c = (q & 255) * 4;
            int b = m >> 9, l = m & 511;
            float4 a = *(const float4*)(cb + c);
            float4 w0 = *(const float4*)(cw + (c + 0) * 4);
            float4 w1 = *(const float4*)(cw + (c + 1) * 4);
            float4 w2 = *(const float4*)(cw + (c + 2) * 4);
            float4 w3 = *(const float4*)(cw + (c + 3) * 4);
            float wa0[4] = {w0.x, w0.y, w0.z, w0.w};
            float wa1[4] = {w1.x, w1.y, w1.z, w1.w};
            float wa2[4] = {w2.x, w2.y, w2.z, w2.w};
            float wa3[4] = {w3.x, w3.y, w3.z, w3.w};
#pragma unroll
            for (int k = 0; k < 4; k++) {
                int ls = l + k - 3;
                if (ls >= 0) {
                    float4 v = *(const float4*)(g_zx + (long)((b << 9) + ls) * D_IN_PROJ + D_INNER + c);
                    a.x = fmaf(v.x, wa0[k], a.x);
                    a.y = fmaf(v.y, wa1[k], a.y);
                    a.z = fmaf(v.z, wa2[k], a.z);
                    a.w = fmaf(v.w, wa3[k], a.w);
                }
            }
            a.x = a.x / (1.f + __expf(-a.x));
            a.y = a.y / (1.f + __expf(-a.y));
            a.z = a.z / (1.f + __expf(-a.z));
            a.w = a.w / (1.f + __expf(-a.w));
            *(float4*)(g_xbc + (long)m * CONV_DIM + c) = a;
        } else {
            int rq = q - CONVXQ;
            int m = rq >> 2, h = (rq & 3) * 4;
#pragma unroll
            for (int j = 0; j < 4; j++) {
                float v = g_zx[(long)m * D_IN_PROJ + D_INNER + CONV_DIM + h + j] + dtb[h + j];
                float dt = (v > 20.f) ? v : log1pf(expf(v));
                float A = -expf(A_log[h + j]);
                g_dt[m * NHEADS + h + j] = dt;
                g_ldA[m * NHEADS + h + j] = dt * A;
            }
        }
    }

    {
        float (*sB64)[65] = (float(*)[65])sh;
        float (*sC8)[65]  = (float(*)[65])(sh + 64 * 65 * 4);
        int cbIdx = bb & 15;
        int half  = (bb >> 4) & 1;
        int slice = bb >> 5;
        int b = cbIdx >> 3, c = cbIdx & 7;
        int mBase = b * SEQ + c * QCH;
        for (int i = tid; i < 64 * 64; i += 256) {
            int s2 = i >> 6, n = i & 63;
            int ch = D_INNER + half * 64 + n;
            int m = mBase + s2;
            float v = conv_silu_1(cw, cb, m, ch);
            sB64[s2][n] = v;
            g_xbc[(long)m * CONV_DIM + ch] = v;
        }
        for (int i = tid; i < 8 * 64; i += 256) {
            int t = i >> 6, n = i & 63;
            int ch = D_INNER + D_STATE + half * 64 + n;
            int m = mBase + slice * 8 + t;
            float v = conv_silu_1(cw, cb, m, ch);
            sC8[t][n] = v;
            g_xbc[(long)m * CONV_DIM + ch] = v;
        }
        __syncthreads();
        int t = tid >> 5;
        long base = (long)cbIdx * (QCH * QCH);
#pragma unroll
        for (int ss = 0; ss < 2; ss++) {
            int s2 = lane + ss * 32;
            float acc = 0.f;
#pragma unroll
            for (int n = 0; n < 64; n++) acc = fmaf(sC8[t][n], sB64[s2][n], acc);
            g_CB[half][base + (slice * 8 + t) * 64 + s2] = acc;
        }
    }
    grid_barrier(barBase + 0);

    // ===== Phase C: cumsum L, G, y_local, S =====
    {
        float (*sA)[68] = (float(*)[68])sh;
        float (*sG)[68] = (float(*)[68])(sh + 64 * 68 * 4);
        float* sL  = (float*)(sh + 2 * 64 * 68 * 4);
        float* sDt = sL + 64;
        int c = bb & 7, bh = bb >> 3;
        int b = bh >> 4, h = bh & 15;
        int mBase = b * SEQ + c * QCH;
        int ty = tid >> 4, tx = tid & 15;
        int t4 = tid >> 2, j16 = (tid & 3) * 16;
        {
            const float* src = g_xbc + (long)(mBase + t4) * CONV_DIM + h * HEADDIM + j16;
#pragma unroll
            for (int q = 0; q < 4; q++) {
                float4 v = *(const float4*)(src + q * 4);
                sA[t4][j16 + q * 4 + 0] = v.x; sA[t4][j16 + q * 4 + 1] = v.y;
                sA[t4][j16 + q * 4 + 2] = v.z; sA[t4][j16 + q * 4 + 3] = v.w;
            }
        }
        if (tid < 64) {
            sDt[tid] = g_dt[(mBase + tid) * NHEADS + h];
            sL[tid]  = g_ldA[(mBase + tid) * NHEADS + h];
        }
        __syncthreads();
        if (tid < 64) {
            float v = sL[tid];
#pragma unroll
            for (int o = 1; o < 32; o <<= 1) {
                float n = __shfl_up_sync(0xffffffffu, v, o);
                if (lane >= o) v += n;
            }
            sL[tid] = v;
        }
        __syncthreads();
        if (tid >= 32 && tid < 64) sL[tid] += sL[31];
        __syncthreads();
        if (tid < 64) {
            g_cumL[bb * QCH + tid] = sL[tid];
            if (tid == 63) g_eLtot[bb] = __expf(sL[63]);
        }
        long cbbase = (long)((b << 3) + c) * (QCH * QCH);
#pragma unroll
        for (int i = 0; i < 4; i++) {
            int t = ty * 4 + i;
#pragma unroll
            for (int j = 0; j < 4; j++) {
                int s2 = tx * 4 + j;
                float g = 0.f;
                if (s2 <= t) {
                    float raw = g_CB[0][cbbase + t * 64 + s2] + g_CB[1][cbbase + t * 64 + s2];
                    g = raw * __expf(sL[t] - sL[s2]) * sDt[s2];
                }
                sG[t][s2] = g;
            }
        }
        __syncthreads();
        {
            float yv[4][4];
#pragma unroll
            for (int i = 0; i < 4; i++)
#pragma unroll
                for (int j = 0; j < 4; j++) yv[i][j] = 0.f;
#pragma unroll 4
            for (int s2 = 0; s2 < 64; s2++) {
                float av[4];
#pragma unroll
                for (int i = 0; i < 4; i++) av[i] = sG[ty * 4 + i][s2];
                float4 b4 = *(const float4*)&sA[s2][tx * 4];
                float bv[4] = {b4.x, b4.y, b4.z, b4.w};
#pragma unroll
                for (int i = 0; i < 4; i++)
#pragma unroll
                    for (int j = 0; j < 4; j++) yv[i][j] = fmaf(av[i], bv[j], yv[i][j]);
            }
            float Dval = Dv[h];
#pragma unroll
            for (int i = 0; i < 4; i++) {
                int t = ty * 4 + i;
#pragma unroll
                for (int j = 0; j < 4; j++) {
                    int p = tx * 4 + j;
                    g_y[(long)(mBase + t) * D_INNER + h * HEADDIM + p] = yv[i][j] + Dval * sA[t][p];
                }
            }
        }
        __syncthreads();
        {
            float w = __expf(sL[63] - sL[t4]) * sDt[t4];
#pragma unroll
            for (int q = 0; q < 16; q++) sA[t4][j16 + q] *= w;
        }
        long sbase = (long)bb * (HEADDIM * D_STATE);
#pragma unroll 1
        for (int nh = 0; nh < 2; nh++) {
            __syncthreads();
            {
                const float* bsrc = g_xbc + (long)(mBase + t4) * CONV_DIM + D_INNER + nh * 64 + j16;
#pragma unroll
                for (int q = 0; q < 4; q++) {
                    float4 v = *(const float4*)(bsrc + q * 4);
                    sG[t4][j16 + q * 4 + 0] = v.x; sG[t4][j16 + q * 4 + 1] = v.y;
                    sG[t4][j16 + q * 4 + 2] = v.z; sG[t4][j16 + q * 4 + 3] = v.w;
                }
            }
            __syncthreads();
            float sv[4][4];
#pragma unroll
            for (int i = 0; i < 4; i++)
#pragma unroll
                for (int j = 0; j < 4; j++) sv[i][j] = 0.f;
#pragma unroll 4
            for (int t = 0; t < 64; t++) {
                float4 a4 = *(const float4*)&sA[t][ty * 4];
                float4 b4 = *(const float4*)&sG[t][tx * 4];
                float av[4] = {a4.x, a4.y, a4.z, a4.w};
                float bv[4] = {b4.x, b4.y, b4.z, b4.w};
#pragma unroll
                for (int i = 0; i < 4; i++)
#pragma unroll
                    for (int j = 0; j < 4; j++) sv[i][j] = fmaf(av[i], bv[j], sv[i][j]);
            }
#pragma unroll
            for (int i = 0; i < 4; i++) {
                int p = ty * 4 + i;
#pragma unroll
                for (int j = 0; j < 4; j++)
                    g_S[sbase + (long)p * D_STATE + nh * 64 + tx * 4 + j] = sv[i][j];
            }
        }
    }
    grid_barrier(barBase + 1);

    // ===== Phase D: inter-chunk recurrence, 256-wide =====
    {
        int bh = bb >> 3, slice = bb & 7;
        float H[4];
#pragma unroll
        for (int k = 0; k < 4; k++) H[k] = 0.f;
#pragma unroll 1
        for (int c = 0; c < NCHUNK; c++) {
            long base = ((long)(bh * NCHUNK + c)) * HEADDIM * D_STATE + slice * 1024;
            float el = g_eLtot[bh * NCHUNK + c];
#pragma unroll
            for (int k = 0; k < 4; k++) {
                long e = base + tid + k * 256;
                g_Hs[e] = H[k];
                H[k] = el * H[k] + g_S[e];
            }
        }
    }
    grid_barrier(barBase + 2);

    // ===== Phase E: y += exp(L_t) * C_t . H_start =====
    {
        float (*sTa)[72] = (float(*)[72])sh;
        float (*sTh)[72] = (float(*)[72])(sh + 16 * 72 * 4);
        float* sEL = (float*)(sh + 2 * 16 * 72 * 4);
        int c = bb & 7, bh = bb >> 3;
        int b = bh >> 4, h = bh & 15;
        int mBase = b * SEQ + c * QCH;
        int ty = tid >> 4, tx = tid & 15;
        if (tid < 64) sEL[tid] = __expf(g_cumL[bb * QCH + tid]);

        float acc[4][4];
#pragma unroll
        for (int i = 0; i < 4; i++)
#pragma unroll
            for (int j = 0; j < 4; j++) acc[i][j] = 0.f;

        long hbase = (long)bb * (HEADDIM * D_STATE);
#pragma unroll 1
        for (int n0 = 0; n0 < D_STATE; n0 += 16) {
            __syncthreads();
            {
                int t = tid >> 2, jj = (tid & 3) * 4;
                float4 cv = *(const float4*)(g_xbc + (long)(mBase + t) * CONV_DIM + D_INNER + D_STATE + n0 + jj);
                sTa[jj + 0][t] = cv.x; sTa[jj + 1][t] = cv.y; sTa[jj + 2][t] = cv.z; sTa[jj + 3][t] = cv.w;
                float4 hv = *(const float4*)(g_Hs + hbase + (long)t * D_STATE + n0 + jj);
                sTh[jj + 0][t] = hv.x; sTh[jj + 1][t] = hv.y; sTh[jj + 2][t] = hv.z; sTh[jj + 3][t] = hv.w;
            }
            __syncthreads();
#pragma unroll
            for (int nn = 0; nn < 16; nn++) {
                float4 a4 = *(const float4*)&sTa[nn][ty * 4];
                float4 b4 = *(const float4*)&sTh[nn][tx * 4];
                float av[4] = {a4.x, a4.y, a4.z, a4.w};
                float bv[4] = {b4.x, b4.y, b4.z, b4.w};
#pragma unroll
                for (int i = 0; i < 4; i++)
#pragma unroll
                    for (int j = 0; j < 4; j++) acc[i][j] = fmaf(av[i], bv[j], acc[i][j]);
            }
        }
#pragma unroll
        for (int i = 0; i < 4; i++) {
            int t = ty * 4 + i;
            float e = sEL[t];
#pragma unroll
            for (int j = 0; j < 4; j++) {
                int p = tx * 4 + j;
                long idx = (long)(mBase + t) * D_INNER + h * HEADDIM + p;
                g_y[idx] += e * acc[i][j];
            }
        }
    }
    grid_barrier(barBase + 3);

    // ===== Phase F: gate + RMSNorm + split =====
    {
        float* red = (float*)sh;
#pragma unroll 1
        for (int rr = 0; rr < 4; rr++) {
            int m = bb * 4 + rr;
            float vals[4];
            float ss = 0.f;
#pragma unroll
            for (int i = 0; i < 4; i++) {
                int c = tid + i * 256;
                float z = g_zx[(long)m * D_IN_PROJ + c];
                float gate = z / (1.f + __expf(-z));
                float v = g_y[(long)m * D_INNER + c] * gate;
                vals[i] = v;
                ss = fmaf(v, v, ss);
            }
#pragma unroll
            for (int o = 16; o; o >>= 1) ss += __shfl_xor_sync(0xffffffffu, ss, o);
            __syncthreads();
            if (lane == 0) red[tid >> 5] = ss;
            __syncthreads();
            float tot = 0.f;
#pragma unroll
            for (int i = 0; i < 8; i++) tot += red[i];
            float rs = rsqrtf(tot * (1.f / D_INNER) + 1e-5f);
#pragma unroll
            for (int i = 0; i < 4; i++) {
                int c = tid + i * 256;
                float v = vals[i] * rs * rw[c];
                split1(v, g_ah[(long)m * D_INNER + c], g_al[(long)m * D_INNER + c]);
            }
        }
    }
}

// ---------------- residual + LayerNorm + split ----------------
__global__ __launch_bounds__(256) void res_ln_split(const float* __restrict__ lw,
                                                    const float* __restrict__ lb) {
    int m = blockIdx.x;
    int t = threadIdx.x;
    __shared__ float red[8];
    long base = (long)m * D_MODEL;
    float v0 = g_y2[base + t]       + g_y2b[base + t]       + g_x[base + t];
    float v1 = g_y2[base + t + 256] + g_y2b[base + t + 256] + g_x[base + t + 256];
    float s = v0 + v1;
#pragma unroll
    for (int o = 16; o; o >>= 1) s += __shfl_xor_sync(0xffffffffu, s, o);
    if ((t & 31) == 0) red[t >> 5] = s;
    __syncthreads();
    float tot = 0.f;
#pragma unroll
    for (int i = 0; i < 8; i++) tot += red[i];
    float mu = tot * (1.f / D_MODEL);
    __syncthreads();
    float c0 = v0 - mu, c1 = v1 - mu;
    float ss = c0 * c0 + c1 * c1;
#pragma unroll
    for (int o = 16; o; o >>= 1) ss += __shfl_xor_sync(0xffffffffu, ss, o);
    if ((t & 31) == 0) red[t >> 5] = ss;
    __syncthreads();
    float vtot = 0.f;
#pragma unroll
    for (int i = 0; i < 8; i++) vtot += red[i];
    float rs = rsqrtf(vtot * (1.f / D_MODEL) + 1e-5f);
    float o0 = c0 * rs * lw[t]       + lb[t];
    float o1 = c1 * rs * lw[t + 256] + lb[t + 256];
    g_x[base + t]       = o0;
    g_x[base + t + 256] = o1;
    split1(o0, g_ah[base + t],       g_al[base + t]);
    split1(o1, g_ah[base + t + 256], g_al[base + t + 256]);
}

// ---------------- launch ----------------
#define DSMA (3 * (256 + 128) * SROW)   // 92160
#define DSMB (4 * (128 + 128) * SROW)   // 81920
extern "C" void kernel_launch(void* const* d_in, const int* in_sizes, int n_in,
                              void* d_out, int out_size) {
    const int*   tokens    = (const int*)  d_in[0];
    const float* embedding = (const float*)d_in[1];
    const float* in_proj_w = (const float*)d_in[2];
    const float* conv_w    = (const float*)d_in[3];
    const float* conv_b    = (const float*)d_in[4];
    const float* dt_bias   = (const float*)d_in[5];
    const float* A_log     = (const float*)d_in[6];
    const float* Dv        = (const float*)d_in[7];
    const float* rms_w     = (const float*)d_in[8];
    const float* out_proj_w= (const float*)d_in[9];
    const float* ln_w      = (const float*)d_in[10];
    const float* ln_b      = (const float*)d_in[11];
    const float* head_w    = (const float*)d_in[12];
    const float* head_b    = (const float*)d_in[13];
    float* out = (float*)d_out;

    cudaFuncSetAttribute(mma_gemm_a, cudaFuncAttributeMaxDynamicSharedMemorySize, DSMA);
    cudaFuncSetAttribute(mma_gemm_b, cudaFuncAttributeMaxDynamicSharedMemorySize, DSMB);

    void *p_zx, *p_y2, *p_y2b, *p_ah, *p_al;
    void *p_whin, *p_wlin, *p_whout, *p_wlout, *p_whhd, *p_wlhd;
    cudaGetSymbolAddress(&p_zx, g_zx);
    cudaGetSymbolAddress(&p_y2, g_y2);
    cudaGetSymbolAddress(&p_y2b, g_y2b);
    cudaGetSymbolAddress(&p_ah, g_ah);
    cudaGetSymbolAddress(&p_al, g_al);
    cudaGetSymbolAddress(&p_whin,  g_wh_in);
    cudaGetSymbolAddress(&p_wlin,  g_wl_in);
    cudaGetSymbolAddress(&p_whout, g_wh_out);
    cudaGetSymbolAddress(&p_wlout, g_wl_out);
    cudaGetSymbolAddress(&p_whhd,  g_wh_hd);
    cudaGetSymbolAddress(&p_wlhd,  g_wl_hd);
    float* dzx  = (float*)p_zx;
    float* dy2  = (float*)p_y2;
    float* dy2b = (float*)p_y2b;
    __nv_bfloat16* ah = (__nv_bfloat16*)p_ah;
    __nv_bfloat16* al = (__nv_bfloat16*)p_al;
    __nv_bfloat16* whin  = (__nv_bfloat16*)p_whin;
    __nv_bfloat16* wlin  = (__nv_bfloat16*)p_wlin;
    __nv_bfloat16* whout = (__nv_bfloat16*)p_whout;
    __nv_bfloat16* wlout = (__nv_bfloat16*)p_wlout;
    __nv_bfloat16* whhd  = (__nv_bfloat16*)p_whhd;
    __nv_bfloat16* wlhd  = (__nv_bfloat16*)p_wlhd;

    prep_kernel<<<(int)((PREP_TOTAL / 4 + 255) / 256), 256>>>(
        in_proj_w, out_proj_w, head_w, tokens, embedding);

    for (int i = 0; i < NB; i++) {
        // in_proj: M128xN64, 3-stage -> 304 CTAs
        mma_gemm_a<<<dim3(NPAD_IN / 64, MROWS / 128, 1), 256, DSMA>>>(
            ah, al, whin + (long)i * NPAD_IN * D_MODEL, wlin + (long)i * NPAD_IN * D_MODEL,
            dzx, D_IN_PROJ, D_MODEL, D_MODEL / 32);
        fused_mid<<<256, 256>>>(
            conv_w + (long)i * CONV_DIM * D_CONV, conv_b + (long)i * CONV_DIM,
            dt_bias + i * NHEADS, A_log + i * NHEADS,
            Dv + i * NHEADS, rms_w + (long)i * D_INNER, i * 4);
        mma_gemm_b<<<dim3(D_MODEL / 64, MROWS / 64, 2), 256, DSMB>>>(
            ah, al, whout + (long)i * D_MODEL * D_INNER, wlout + (long)i * D_MODEL * D_INNER,
            nullptr, dy2, dy2b, D_MODEL, D_INNER, 512 / 32, 512);
        res_ln_split<<<MROWS, 256>>>(ln_w + i * D_MODEL, ln_b + i * D_MODEL);
    }

    mma_gemm_b<<<dim3(NPAD_HD / 64, MROWS / 64, 1), 256, DSMB>>>(
        ah, al, whhd, wlhd, head_b, out, nullptr, LABELS, D_MODEL, D_MODEL / 32, 0);
}